// round 9
// baseline (speedup 1.0000x reference)
#include <cuda_runtime.h>
#include <cuda_fp16.h>
#include <math.h>
#include <stdint.h>

#define N_NODES 10000
#define IN_DIMS 128
#define EMB 64
#define HID 64
#define NEG_SLOPE 0.2f
#define TILE 128
#define NT 79                 // ceil(N/128)
#define NPAD (NT*TILE)        // 10112
#define MAXEDGE 400000
#define KS 128                // [hi(64) | lo(64)] fp16 split rows

// ---------------- scratch (no allocations allowed) ----------------
__device__ float    g_hp[N_NODES*HID];
__device__ float    g_asrc[N_NODES];
__device__ float    g_adst[N_NODES];
__device__ float    g_embP[N_NODES*HID];
__device__ float    g_attr_part[IN_DIMS*EMB];
__device__ float    g_xa2[IN_DIMS*HID];
// zero-initialized at module load; pad rows (>= N_NODES) are never written
__device__ __align__(16) __half g_Ehf[NPAD*KS];
// CSR scratch: g_deg zeroed at load AND re-zeroed inside k_edges each run
__device__ int g_deg[N_NODES];
__device__ int g_off[N_NODES + 1];
__device__ int g_pos[N_NODES];
__device__ int2 g_epack[MAXEDGE + N_NODES];   // (src, float-bits of w)
// software grid barrier
__device__ int g_bar_count;
__device__ volatile int g_bar_gen;

#define EB_BLOCKS 148
#define EB_THREADS 1024

__device__ __forceinline__ void gridbar() {
    __syncthreads();
    if (threadIdx.x == 0) {
        int gen = g_bar_gen;
        __threadfence();
        if (atomicAdd(&g_bar_count, 1) == EB_BLOCKS - 1) {
            g_bar_count = 0;
            __threadfence();
            g_bar_gen = gen + 1;
        } else {
            while (g_bar_gen == gen) { }
        }
        __threadfence();
    }
    __syncthreads();
}

// ===== fused encoder: hp = relu(x@W1+b1)@W2 ; a_src/a_dst dot products =====
extern __shared__ float s_enc[];
__global__ __launch_bounds__(256) void k_enc(const float* __restrict__ x,
                                             const float* __restrict__ W1,
                                             const float* __restrict__ b1,
                                             const float* __restrict__ W2,
                                             const float* __restrict__ att_s,
                                             const float* __restrict__ att_d) {
    float* Ws1 = s_enc;
    float* Ws2 = s_enc + 8192;
    float* xs  = s_enc + 12288;
    float* hs  = s_enc + 14336;
    __shared__ float As[HID], Ad[HID], Bs1[EMB];

    int t = threadIdx.x;
    int nbase = blockIdx.x * 16;

    #pragma unroll
    for (int i = 0; i < 8; i++)
        ((float4*)Ws1)[t + i*256] = ((const float4*)W1)[t + i*256];
    #pragma unroll
    for (int i = 0; i < 4; i++)
        ((float4*)Ws2)[t + i*256] = ((const float4*)W2)[t + i*256];
    #pragma unroll
    for (int i = 0; i < 2; i++)
        ((float4*)xs)[t + i*256] =
            ((const float4*)x)[(size_t)nbase*32 + t + i*256];
    if (t < HID) { As[t] = att_s[t]; Ad[t] = att_d[t]; }
    else if (t < 128) { Bs1[t - HID] = b1[t - HID]; }
    __syncthreads();

    int nl = t >> 4;
    int e0 = (t & 15) * 4;

    {
        float a0=0.f, a1=0.f, a2=0.f, a3=0.f;
        const float* xr = &xs[nl*IN_DIMS];
        #pragma unroll 4
        for (int k = 0; k < IN_DIMS; k++) {
            float xv = xr[k];
            float4 w = *(const float4*)&Ws1[k*EMB + e0];
            a0 += xv*w.x; a1 += xv*w.y; a2 += xv*w.z; a3 += xv*w.w;
        }
        *(float4*)&hs[nl*EMB + e0] = make_float4(
            fmaxf(a0 + Bs1[e0+0], 0.f), fmaxf(a1 + Bs1[e0+1], 0.f),
            fmaxf(a2 + Bs1[e0+2], 0.f), fmaxf(a3 + Bs1[e0+3], 0.f));
    }
    __syncthreads();

    {
        float a0=0.f, a1=0.f, a2=0.f, a3=0.f;
        const float* hr = &hs[nl*EMB];
        #pragma unroll 8
        for (int k = 0; k < EMB; k++) {
            float hv = hr[k];
            float4 w = *(const float4*)&Ws2[k*HID + e0];
            a0 += hv*w.x; a1 += hv*w.y; a2 += hv*w.z; a3 += hv*w.w;
        }
        int n = nbase + nl;
        *(float4*)&g_hp[(size_t)n*HID + e0] = make_float4(a0, a1, a2, a3);
        float ps = a0*As[e0] + a1*As[e0+1] + a2*As[e0+2] + a3*As[e0+3];
        float pd = a0*Ad[e0] + a1*Ad[e0+1] + a2*Ad[e0+2] + a3*Ad[e0+3];
        #pragma unroll
        for (int o = 8; o; o >>= 1) {
            ps += __shfl_down_sync(0xffffffffu, ps, o, 16);
            pd += __shfl_down_sync(0xffffffffu, pd, o, 16);
        }
        if ((t & 15) == 0) { g_asrc[n] = ps; g_adst[n] = pd; }
    }
}

// ===== fused edge pipeline: count -> scan -> scatter (one kernel) =====
__global__ __launch_bounds__(EB_THREADS) void k_edges(const int* __restrict__ ei, int E) {
    int EN = E + N_NODES;
    int gtid = blockIdx.x * EB_THREADS + threadIdx.x;
    const int gsz = EB_BLOCKS * EB_THREADS;

    for (int i = gtid; i < EN; i += gsz) {
        int d = (i < E) ? ei[E + i] : (i - E);
        atomicAdd(&g_deg[d], 1);
    }
    gridbar();

    if (blockIdx.x == 0) {
        __shared__ int wsum[32];
        int t = threadIdx.x, lane = t & 31, wid = t >> 5;
        int base = t * 10;
        int v[10];
        int tot = 0;
        #pragma unroll
        for (int j = 0; j < 10; j++) {
            int idx = base + j;
            v[j] = (idx < N_NODES) ? g_deg[idx] : 0;
            tot += v[j];
        }
        int s = tot;
        #pragma unroll
        for (int o = 1; o < 32; o <<= 1) {
            int nv = __shfl_up_sync(0xffffffffu, s, o);
            if (lane >= o) s += nv;
        }
        if (lane == 31) wsum[wid] = s;
        __syncthreads();
        if (wid == 0) {
            int ws = wsum[lane];
            #pragma unroll
            for (int o = 1; o < 32; o <<= 1) {
                int nv = __shfl_up_sync(0xffffffffu, ws, o);
                if (lane >= o) ws += nv;
            }
            wsum[lane] = ws;
        }
        __syncthreads();
        int wex = wid ? wsum[wid - 1] : 0;
        int run = wex + s - tot;
        #pragma unroll
        for (int j = 0; j < 10; j++) {
            int idx = base + j;
            if (idx < N_NODES) {
                g_off[idx] = run;
                g_pos[idx] = run;
                g_deg[idx] = 0;
                run += v[j];
                if (idx == N_NODES - 1) g_off[N_NODES] = run;
            }
        }
    }
    gridbar();

    for (int i = gtid; i < EN; i += gsz) {
        int s, d;
        if (i < E) { s = ei[i]; d = ei[E + i]; } else { s = d = i - E; }
        float e = g_asrc[s] + g_adst[d];
        e = (e > 0.f) ? e : NEG_SLOPE * e;
        float w = __expf(e);
        int pos = atomicAdd(&g_pos[d], 1);
        g_epack[pos] = make_int2(s, __float_as_int(w));
    }
}

// warp per dst: softmax aggregation + bias + fp16 hi/lo split
__global__ void k_aggr(const float* __restrict__ bg) {
    int d = (blockIdx.x * blockDim.x + threadIdx.x) >> 5;
    int lane = threadIdx.x & 31;
    if (d >= N_NODES) return;
    int beg = g_off[d], end = g_off[d + 1];
    float wsum = 0.f, a0 = 0.f, a1 = 0.f;
    for (int p = beg; p < end; p++) {
        int2 pk = g_epack[p];
        float w = __int_as_float(pk.y);
        wsum += w;
        a0 += g_hp[(size_t)pk.x*HID + lane]      * w;
        a1 += g_hp[(size_t)pk.x*HID + 32 + lane] * w;
    }
    float inv = 1.f / wsum;
    float v0 = a0 * inv + bg[lane];
    float v1 = a1 * inv + bg[lane + 32];
    g_embP[(size_t)d*HID + lane]      = v0;
    g_embP[(size_t)d*HID + 32 + lane] = v1;
    __half h0 = __float2half(v0);
    __half l0 = __float2half(v0 - __half2float(h0));
    __half h1 = __float2half(v1);
    __half l1 = __float2half(v1 - __half2float(h1));
    size_t eb = (size_t)d * KS;
    g_Ehf[eb + lane]      = h0;
    g_Ehf[eb + 32 + lane] = h1;
    g_Ehf[eb + 64 + lane] = l0;
    g_Ehf[eb + 96 + lane] = l1;
}

// attr_part zeroed here (runs first in the new order, before its own atomics)
__global__ __launch_bounds__(256) void k_attr1(const float* __restrict__ x,
                                               const float* __restrict__ W1,
                                               int zero_first) {
    __shared__ float xs[10][IN_DIMS];
    __shared__ float ws[10][EMB];
    int t = threadIdx.x;
    int i0 = (t >> 4) * 8;
    int e0 = (t & 15) * 4;
    float acc[8][4];
    #pragma unroll
    for (int a = 0; a < 8; a++)
        #pragma unroll
        for (int b = 0; b < 4; b++) acc[a][b] = 0.f;
    int rbase = blockIdx.x * 100;
    for (int c = 0; c < 10; c++) {
        for (int i = t; i < 10*IN_DIMS; i += 256) {
            int r = rbase + c*10 + i / IN_DIMS;
            xs[i / IN_DIMS][i % IN_DIMS] = x[(size_t)r*IN_DIMS + (i % IN_DIMS)];
        }
        for (int i = t; i < 10*EMB; i += 256) {
            int r = rbase + c*10 + i / EMB;
            ws[i / EMB][i % EMB] = W1[(size_t)r*EMB + (i % EMB)];
        }
        __syncthreads();
        #pragma unroll
        for (int rr = 0; rr < 10; rr++) {
            float wv[4];
            #pragma unroll
            for (int j = 0; j < 4; j++) wv[j] = ws[rr][e0 + j];
            #pragma unroll
            for (int ii = 0; ii < 8; ii++) {
                float xv = xs[rr][i0 + ii];
                #pragma unroll
                for (int j = 0; j < 4; j++) acc[ii][j] += xv * wv[j];
            }
        }
        __syncthreads();
    }
    #pragma unroll
    for (int ii = 0; ii < 8; ii++)
        #pragma unroll
        for (int j = 0; j < 4; j++) {
            float* dst = &g_attr_part[(i0+ii)*EMB + e0 + j];
            if (zero_first && blockIdx.x == 0) ;  // placeholder, see note
            atomicAdd(dst, acc[ii][j]);
        }
}

// zero attr_part between graph replays (tiny, merged into first real launch
// is unsafe due to atomics ordering; keep as micro-kernel, 1 launch ~2us)
__global__ void k_azero() {
    int i = blockIdx.x * blockDim.x + threadIdx.x;
    if (i < IN_DIMS*EMB) g_attr_part[i] = 0.f;
}

__global__ __launch_bounds__(256) void k_attr2(const float* __restrict__ b1,
                                               const float* __restrict__ W2,
                                               const float* __restrict__ b2) {
    __shared__ float xa1[IN_DIMS*EMB];
    __shared__ float W2s[EMB*HID];
    int t = threadIdx.x;
    for (int i = t; i < IN_DIMS*EMB; i += 256)
        xa1[i] = fmaxf(g_attr_part[i] + b1[i % EMB], 0.f);
    for (int i = t; i < EMB*HID; i += 256) W2s[i] = W2[i];
    __syncthreads();
    int i0 = (t >> 4) * 8;
    int h0 = (t & 15) * 4;
    float acc[8][4];
    #pragma unroll
    for (int a = 0; a < 8; a++)
        #pragma unroll
        for (int b = 0; b < 4; b++) acc[a][b] = 0.f;
    for (int k = 0; k < EMB; k++) {
        float wv[4];
        #pragma unroll
        for (int j = 0; j < 4; j++) wv[j] = W2s[k*HID + h0 + j];
        #pragma unroll
        for (int ii = 0; ii < 8; ii++) {
            float xv = xa1[(i0+ii)*EMB + k];
            #pragma unroll
            for (int j = 0; j < 4; j++) acc[ii][j] += xv * wv[j];
        }
    }
    #pragma unroll
    for (int ii = 0; ii < 8; ii++)
        #pragma unroll
        for (int j = 0; j < 4; j++)
            g_xa2[(i0+ii)*HID + h0 + j] = acc[ii][j] + b2[h0 + j];
}

__global__ __launch_bounds__(256) void k_xout(float* __restrict__ out) {
    __shared__ float xa[IN_DIMS*(HID+1)];
    __shared__ float es[32*HID];
    int t = threadIdx.x;
    for (int i = t; i < IN_DIMS*HID; i += 256) {
        int r = i / HID, c = i % HID;
        xa[r*(HID+1) + c] = g_xa2[i];
    }
    int nb = blockIdx.x * 32;
    for (int i = t; i < 32*HID; i += 256) es[i] = g_embP[(size_t)nb*HID + i];
    __syncthreads();
    int nl = t >> 3;
    int ib = (t & 7) * 16;
    const float* e = &es[nl*HID];
    int n = nb + nl;
    if (n >= N_NODES) return;
    for (int ii = 0; ii < 16; ii++) {
        int i = ib + ii;
        const float* w = &xa[i*(HID+1)];
        float acc = 0.f;
        #pragma unroll 8
        for (int k = 0; k < HID; k++) acc += e[k]*w[k];
        out[(size_t)n*IN_DIMS + i] = acc;
    }
}

// ===== s_ GEMM: 2-pass fp16 split (hi*hi + lo*hi), fp32 acc, shared B =====
#define ROWB 272
#define BOFF 34816
#define SMEM_S (2*34816)
#define TRS 132

__device__ __forceinline__ uint32_t smem_u32(const void* p) {
    uint32_t a;
    asm("{ .reg .u64 t; cvta.to.shared.u64 t, %1; cvt.u32.u64 %0, t; }" : "=r"(a) : "l"(p));
    return a;
}
__device__ __forceinline__ void ldsm4(uint32_t addr, uint32_t& r0, uint32_t& r1,
                                      uint32_t& r2, uint32_t& r3) {
    asm volatile("ldmatrix.sync.aligned.m8n8.x4.shared.b16 {%0,%1,%2,%3}, [%4];"
                 : "=r"(r0), "=r"(r1), "=r"(r2), "=r"(r3) : "r"(addr));
}
__device__ __forceinline__ void mma_f32(float c[4], uint32_t a0, uint32_t a1,
                                        uint32_t a2, uint32_t a3,
                                        uint32_t b0, uint32_t b1) {
    asm volatile(
        "mma.sync.aligned.m16n8k16.row.col.f32.f16.f16.f32 "
        "{%0,%1,%2,%3}, {%4,%5,%6,%7}, {%8,%9}, {%0,%1,%2,%3};"
        : "+f"(c[0]), "+f"(c[1]), "+f"(c[2]), "+f"(c[3])
        : "r"(a0), "r"(a1), "r"(a2), "r"(a3), "r"(b0), "r"(b1));
}

extern __shared__ char smem_s[];

__global__ __launch_bounds__(256, 3) void k_s_mma(float* __restrict__ sout) {
    int b = blockIdx.x;
    int ti = 0;
    {
        int rem = b, rowlen = NT;
        while (rem >= rowlen) { rem -= rowlen; ti++; rowlen--; }
        b = rem;
    }
    int tj = ti + b;

    int t = threadIdx.x;
    int warp = t >> 5, lane = t & 31;
    int wm = warp >> 1, wn = warp & 1;
    int g = lane >> 2, tq = lane & 3;
    int q = lane >> 3, r8 = lane & 7;

    const __half* gA = &g_Ehf[(size_t)ti * TILE * KS];
    const __half* gB = &g_Ehf[(size_t)tj * TILE * KS];
    #pragma unroll
    for (int i = 0; i < 8; i++) {
        int v = i * 256 + t;
        int row = v >> 4;
        int c16 = v & 15;
        *(float4*)(smem_s + row*ROWB + c16*16) = *(const float4*)(gA + row*KS + c16*8);
    }
    #pragma unroll
    for (int i = 0; i < 4; i++) {
        int v = i * 256 + t;
        int row = v >> 3;
        int c8 = v & 7;
        *(float4*)(smem_s + BOFF + row*ROWB + c8*16) = *(const float4*)(gB + row*KS + c8*8);
    }
    __syncthreads();

    uint32_t sA = smem_u32(smem_s);
    uint32_t sB = sA + BOFF;

    uint32_t aAddr[2], bAddr[4];
    #pragma unroll
    for (int mt = 0; mt < 2; mt++)
        aAddr[mt] = sA + (uint32_t)(wm*32 + mt*16 + r8 + (q & 1)*8)*ROWB + (uint32_t)((q >> 1)*8)*2;
    #pragma unroll
    for (int n2 = 0; n2 < 4; n2++)
        bAddr[n2] = sB + (uint32_t)(wn*64 + n2*16 + r8 + (q >> 1)*8)*ROWB + (uint32_t)((q & 1)*8)*2;

    float c[2][8][4];
    #pragma unroll
    for (int mt = 0; mt < 2; mt++)
        #pragma unroll
        for (int nt = 0; nt < 8; nt++)
            #pragma unroll
            for (int rr = 0; rr < 4; rr++) c[mt][nt][rr] = 0.f;

    #pragma unroll
    for (int kk = 0; kk < 4; kk++) {
        uint32_t ka = (uint32_t)kk * 32;
        uint32_t ah[2][4], al[2][4];
        #pragma unroll
        for (int mt = 0; mt < 2; mt++) {
            ldsm4(aAddr[mt] + ka,       ah[mt][0], ah[mt][1], ah[mt][2], ah[mt][3]);
            ldsm4(aAddr[mt] + 128 + ka, al[mt][0], al[mt][1], al[mt][2], al[mt][3]);
        }
        #pragma unroll
        for (int n2 = 0; n2 < 4; n2++) {
            uint32_t b0, b1, b2, b3;
            ldsm4(bAddr[n2] + ka, b0, b1, b2, b3);
            int nt = n2 * 2;
            mma_f32(c[0][nt],   ah[0][0], ah[0][1], ah[0][2], ah[0][3], b0, b1);
            mma_f32(c[1][nt],   ah[1][0], ah[1][1], ah[1][2], ah[1][3], b0, b1);
            mma_f32(c[0][nt+1], ah[0][0], ah[0][1], ah[0][2], ah[0][3], b2, b3);
            mma_f32(c[1][nt+1], ah[1][0], ah[1][1], ah[1][2], ah[1][3], b2, b3);
            mma_f32(c[0][nt],   al[0][0], al[0][1], al[0][2], al[0][3], b0, b1);
            mma_f32(c[1][nt],   al[1][0], al[1][1], al[1][2], al[1][3], b0, b1);
            mma_f32(c[0][nt+1], al[0][0], al[0][1], al[0][2], al[0][3], b2, b3);
            mma_f32(c[1][nt+1], al[1][0], al[1][1], al[1][2], al[1][3], b2, b3);
        }
    }

    #pragma unroll
    for (int mt = 0; mt < 2; mt++)
        #pragma unroll
        for (int nt = 0; nt < 8; nt++)
            #pragma unroll
            for (int rr = 0; rr < 4; rr++)
                c[mt][nt][rr] = 1.f / (1.f + __expf(-c[mt][nt][rr]));

    #pragma unroll
    for (int mt = 0; mt < 2; mt++) {
        #pragma unroll
        for (int rr = 0; rr < 2; rr++) {
            int gr = ti*TILE + wm*32 + mt*16 + g + rr*8;
            if (gr >= N_NODES) continue;
            size_t obase = (size_t)gr * N_NODES;
            #pragma unroll
            for (int nt = 0; nt < 8; nt++) {
                int gc = tj*TILE + wn*64 + nt*8 + tq*2;
                if (gc < N_NODES)
                    *(float2*)&sout[obase + gc] =
                        make_float2(c[mt][nt][rr*2], c[mt][nt][rr*2 + 1]);
            }
        }
    }

    if (ti != tj) {
        __syncthreads();
        float* tr = (float*)smem_s;
        #pragma unroll
        for (int mt = 0; mt < 2; mt++) {
            #pragma unroll
            for (int rr = 0; rr < 2; rr++) {
                int lr = wm*32 + mt*16 + g + rr*8;
                #pragma unroll
                for (int nt = 0; nt < 8; nt++) {
                    int lc = wn*64 + nt*8 + tq*2;
                    tr[lc*TRS + lr]     = c[mt][nt][rr*2];
                    tr[(lc+1)*TRS + lr] = c[mt][nt][rr*2 + 1];
                }
            }
        }
        __syncthreads();
        int len = N_NODES - ti*TILE;
        if (len > TILE) len = TILE;
        int lr0 = lane * 4;
        #pragma unroll
        for (int rr2 = 0; rr2 < 16; rr2++) {
            int lc = warp*16 + rr2;
            int gcRow = tj*TILE + lc;
            if (gcRow < N_NODES && lr0 < len) {
                *(float4*)&sout[(size_t)gcRow*N_NODES + ti*TILE + lr0] =
                    *(float4*)&tr[lc*TRS + lr0];
            }
        }
    }
}

// ---------------- launch ----------------
extern "C" void kernel_launch(void* const* d_in, const int* in_sizes, int n_in,
                              void* d_out, int out_size) {
    const float* x       = (const float*)d_in[0];
    const int*   ei      = (const int*)d_in[1];
    const float* W_stru  = (const float*)d_in[3];
    const float* b_stru  = (const float*)d_in[4];
    const float* W_gat   = (const float*)d_in[5];
    const float* att_src = (const float*)d_in[6];
    const float* att_dst = (const float*)d_in[7];
    const float* b_gat   = (const float*)d_in[8];
    const float* W_attr1 = (const float*)d_in[9];
    const float* b_attr1 = (const float*)d_in[10];
    const float* W_attr2 = (const float*)d_in[11];
    const float* b_attr2 = (const float*)d_in[12];

    int E = in_sizes[1] / 2;

    float* out   = (float*)d_out;
    float* x_out = out;
    float* s_out = out + (size_t)N_NODES * IN_DIMS;

    cudaFuncSetAttribute(k_enc, cudaFuncAttributeMaxDynamicSharedMemorySize, 61440);
    cudaFuncSetAttribute(k_s_mma, cudaFuncAttributeMaxDynamicSharedMemorySize, SMEM_S);

    // order chosen so launch #4 (= ncu capture slot) is k_edges
    k_azero <<<(IN_DIMS*EMB + 255) / 256, 256>>>();
    k_attr1 <<<100, 256>>>(x, W_attr1, 0);
    k_enc   <<<N_NODES / 16, 256, 61440>>>(x, W_stru, b_stru, W_gat, att_src, att_dst);
    k_edges <<<EB_BLOCKS, EB_THREADS>>>(ei, E);
    k_aggr  <<<(N_NODES * 32 + 255) / 256, 256>>>(b_gat);
    k_attr2 <<<1, 256>>>(b_attr1, W_attr2, b_attr2);
    k_xout  <<<(N_NODES + 31) / 32, 256>>>(x_out);
    k_s_mma <<<NT * (NT + 1) / 2, 256, SMEM_S>>>(s_out);
}

// round 10
// speedup vs baseline: 1.0653x; 1.0653x over previous
#include <cuda_runtime.h>
#include <cuda_fp16.h>
#include <math.h>
#include <stdint.h>

#define N_NODES 10000
#define IN_DIMS 128
#define EMB 64
#define HID 64
#define NEG_SLOPE 0.2f
#define TILE 128
#define NT 79                 // ceil(N/128)
#define NPAD (NT*TILE)        // 10112
#define MAXEDGE 400000
#define KS 128                // [hi(64) | lo(64)] fp16 split rows

// ---------------- scratch (no allocations allowed) ----------------
__device__ float    g_hp[N_NODES*HID];
__device__ float    g_asrc[N_NODES];
__device__ float    g_adst[N_NODES];
__device__ float    g_embP[N_NODES*HID];
__device__ float    g_attr_part[IN_DIMS*EMB];
__device__ float    g_xa2[IN_DIMS*HID];
// zero-initialized at module load; pad rows (>= N_NODES) are never written
__device__ __align__(16) __half g_Ehf[NPAD*KS];
// CSR scratch: g_deg zeroed at load AND re-zeroed by k_scan each run
__device__ int g_deg[N_NODES];
__device__ int g_off[N_NODES + 1];
__device__ int g_pos[N_NODES];
__device__ int2 g_epack[MAXEDGE + N_NODES];   // (src, float-bits of w)

// ===== zero attr_part between graph replays =====
__global__ void k_azero() {
    int i = blockIdx.x * blockDim.x + threadIdx.x;
    if (i < IN_DIMS*EMB) g_attr_part[i] = 0.f;
}

// ===== degree count =====
__global__ void k_edge1(const int* __restrict__ ei, int E) {
    int i = blockIdx.x * blockDim.x + threadIdx.x;
    if (i >= E + N_NODES) return;
    int d = (i < E) ? ei[E + i] : (i - E);
    atomicAdd(&g_deg[d], 1);
}

// ===== 3-barrier block scan; writes off+pos; self-cleans deg =====
__global__ __launch_bounds__(1024) void k_scan() {
    __shared__ int wsum[32];
    int t = threadIdx.x, lane = t & 31, wid = t >> 5;
    int base = t * 10;
    int v[10];
    int tot = 0;
    #pragma unroll
    for (int j = 0; j < 10; j++) {
        int idx = base + j;
        v[j] = (idx < N_NODES) ? g_deg[idx] : 0;
        tot += v[j];
    }
    int s = tot;
    #pragma unroll
    for (int o = 1; o < 32; o <<= 1) {
        int nv = __shfl_up_sync(0xffffffffu, s, o);
        if (lane >= o) s += nv;
    }
    if (lane == 31) wsum[wid] = s;
    __syncthreads();
    if (wid == 0) {
        int ws = wsum[lane];
        #pragma unroll
        for (int o = 1; o < 32; o <<= 1) {
            int nv = __shfl_up_sync(0xffffffffu, ws, o);
            if (lane >= o) ws += nv;
        }
        wsum[lane] = ws;
    }
    __syncthreads();
    int wex = wid ? wsum[wid - 1] : 0;
    int run = wex + s - tot;
    #pragma unroll
    for (int j = 0; j < 10; j++) {
        int idx = base + j;
        if (idx < N_NODES) {
            g_off[idx] = run;
            g_pos[idx] = run;
            g_deg[idx] = 0;
            run += v[j];
            if (idx == N_NODES - 1) g_off[N_NODES] = run;
        }
    }
}

// ===== fused encoder, 32 nodes/block: hp = relu(x@W1+b1)@W2 ; attn dots =====
extern __shared__ float s_enc[];
__global__ __launch_bounds__(256) void k_enc(const float* __restrict__ x,
                                             const float* __restrict__ W1,
                                             const float* __restrict__ b1,
                                             const float* __restrict__ W2,
                                             const float* __restrict__ att_s,
                                             const float* __restrict__ att_d) {
    float* Ws1 = s_enc;            //  8192 floats
    float* Ws2 = s_enc + 8192;     //  4096
    float* xs  = s_enc + 12288;    //  4096 (32 x 128)
    float* hs  = s_enc + 16384;    //  2048 (32 x 64)
    __shared__ float As[HID], Ad[HID], Bs1[EMB];

    int t = threadIdx.x;
    int nbase = blockIdx.x * 32;

    #pragma unroll
    for (int i = 0; i < 8; i++)
        ((float4*)Ws1)[t + i*256] = ((const float4*)W1)[t + i*256];
    #pragma unroll
    for (int i = 0; i < 4; i++)
        ((float4*)Ws2)[t + i*256] = ((const float4*)W2)[t + i*256];
    #pragma unroll
    for (int i = 0; i < 4; i++) {
        int v = t + i*256;                 // 0..1023 float4 within block tile
        int n = nbase + (v >> 5);
        ((float4*)xs)[v] = (n < N_NODES)
            ? ((const float4*)x)[(size_t)nbase*32 + v] : make_float4(0,0,0,0);
    }
    if (t < HID) { As[t] = att_s[t]; Ad[t] = att_d[t]; }
    else if (t < 128) { Bs1[t - HID] = b1[t - HID]; }
    __syncthreads();

    int nl = t >> 4;          // 0..15
    int e0 = (t & 15) * 4;

    // phase 1: h = relu(x@W1 + b1), two nodes per thread
    #pragma unroll
    for (int it = 0; it < 2; it++) {
        int row = nl + it*16;
        float a0=0.f, a1=0.f, a2=0.f, a3=0.f;
        const float* xr = &xs[row*IN_DIMS];
        #pragma unroll 4
        for (int k = 0; k < IN_DIMS; k++) {
            float xv = xr[k];
            float4 w = *(const float4*)&Ws1[k*EMB + e0];
            a0 += xv*w.x; a1 += xv*w.y; a2 += xv*w.z; a3 += xv*w.w;
        }
        *(float4*)&hs[row*EMB + e0] = make_float4(
            fmaxf(a0 + Bs1[e0+0], 0.f), fmaxf(a1 + Bs1[e0+1], 0.f),
            fmaxf(a2 + Bs1[e0+2], 0.f), fmaxf(a3 + Bs1[e0+3], 0.f));
    }
    __syncthreads();

    // phase 2: hp = h@W2, attention partials, two nodes per thread
    #pragma unroll
    for (int it = 0; it < 2; it++) {
        int row = nl + it*16;
        int n = nbase + row;
        float a0=0.f, a1=0.f, a2=0.f, a3=0.f;
        const float* hr = &hs[row*EMB];
        #pragma unroll 8
        for (int k = 0; k < EMB; k++) {
            float hv = hr[k];
            float4 w = *(const float4*)&Ws2[k*HID + e0];
            a0 += hv*w.x; a1 += hv*w.y; a2 += hv*w.z; a3 += hv*w.w;
        }
        if (n < N_NODES)
            *(float4*)&g_hp[(size_t)n*HID + e0] = make_float4(a0, a1, a2, a3);
        float ps = a0*As[e0] + a1*As[e0+1] + a2*As[e0+2] + a3*As[e0+3];
        float pd = a0*Ad[e0] + a1*Ad[e0+1] + a2*Ad[e0+2] + a3*Ad[e0+3];
        #pragma unroll
        for (int o = 8; o; o >>= 1) {
            ps += __shfl_down_sync(0xffffffffu, ps, o, 16);
            pd += __shfl_down_sync(0xffffffffu, pd, o, 16);
        }
        if ((t & 15) == 0 && n < N_NODES) { g_asrc[n] = ps; g_adst[n] = pd; }
    }
}

// ===== weight + scatter into CSR slots =====
__global__ void k_edge2(const int* __restrict__ ei, int E) {
    int i = blockIdx.x * blockDim.x + threadIdx.x;
    if (i >= E + N_NODES) return;
    int s, d;
    if (i < E) { s = ei[i]; d = ei[E + i]; } else { s = d = i - E; }
    float e = g_asrc[s] + g_adst[d];
    e = (e > 0.f) ? e : NEG_SLOPE * e;
    float w = __expf(e);
    int pos = atomicAdd(&g_pos[d], 1);
    g_epack[pos] = make_int2(s, __float_as_int(w));
}

// ===== warp per dst, 4x unrolled gathers (MLP), bias + fp16 split =====
__global__ void k_aggr(const float* __restrict__ bg) {
    int d = (blockIdx.x * blockDim.x + threadIdx.x) >> 5;
    int lane = threadIdx.x & 31;
    if (d >= N_NODES) return;
    int beg = g_off[d], end = g_off[d + 1];
    float wsum = 0.f, a0 = 0.f, a1 = 0.f;
    int p = beg;
    for (; p + 4 <= end; p += 4) {
        int2 e0 = g_epack[p];
        int2 e1 = g_epack[p+1];
        int2 e2 = g_epack[p+2];
        int2 e3 = g_epack[p+3];
        const float* r0 = &g_hp[(size_t)e0.x * HID];
        const float* r1 = &g_hp[(size_t)e1.x * HID];
        const float* r2 = &g_hp[(size_t)e2.x * HID];
        const float* r3 = &g_hp[(size_t)e3.x * HID];
        float h00 = r0[lane],    h01 = r0[32+lane];
        float h10 = r1[lane],    h11 = r1[32+lane];
        float h20 = r2[lane],    h21 = r2[32+lane];
        float h30 = r3[lane],    h31 = r3[32+lane];
        float w0 = __int_as_float(e0.y);
        float w1 = __int_as_float(e1.y);
        float w2 = __int_as_float(e2.y);
        float w3 = __int_as_float(e3.y);
        wsum += (w0 + w1) + (w2 + w3);
        a0 += h00*w0 + h10*w1 + h20*w2 + h30*w3;
        a1 += h01*w0 + h11*w1 + h21*w2 + h31*w3;
    }
    for (; p < end; p++) {
        int2 pk = g_epack[p];
        float w = __int_as_float(pk.y);
        const float* r = &g_hp[(size_t)pk.x * HID];
        wsum += w;
        a0 += r[lane] * w;
        a1 += r[32+lane] * w;
    }
    float inv = 1.f / wsum;
    float v0 = a0 * inv + bg[lane];
    float v1 = a1 * inv + bg[lane + 32];
    g_embP[(size_t)d*HID + lane]      = v0;
    g_embP[(size_t)d*HID + 32 + lane] = v1;
    __half h0 = __float2half(v0);
    __half l0 = __float2half(v0 - __half2float(h0));
    __half h1 = __float2half(v1);
    __half l1 = __float2half(v1 - __half2float(h1));
    size_t eb = (size_t)d * KS;
    g_Ehf[eb + lane]      = h0;
    g_Ehf[eb + 32 + lane] = h1;
    g_Ehf[eb + 64 + lane] = l0;
    g_Ehf[eb + 96 + lane] = l1;
}

__global__ __launch_bounds__(256) void k_attr1(const float* __restrict__ x,
                                               const float* __restrict__ W1) {
    __shared__ float xs[10][IN_DIMS];
    __shared__ float ws[10][EMB];
    int t = threadIdx.x;
    int i0 = (t >> 4) * 8;
    int e0 = (t & 15) * 4;
    float acc[8][4];
    #pragma unroll
    for (int a = 0; a < 8; a++)
        #pragma unroll
        for (int b = 0; b < 4; b++) acc[a][b] = 0.f;
    int rbase = blockIdx.x * 100;
    for (int c = 0; c < 10; c++) {
        for (int i = t; i < 10*IN_DIMS; i += 256) {
            int r = rbase + c*10 + i / IN_DIMS;
            xs[i / IN_DIMS][i % IN_DIMS] = x[(size_t)r*IN_DIMS + (i % IN_DIMS)];
        }
        for (int i = t; i < 10*EMB; i += 256) {
            int r = rbase + c*10 + i / EMB;
            ws[i / EMB][i % EMB] = W1[(size_t)r*EMB + (i % EMB)];
        }
        __syncthreads();
        #pragma unroll
        for (int rr = 0; rr < 10; rr++) {
            float wv[4];
            #pragma unroll
            for (int j = 0; j < 4; j++) wv[j] = ws[rr][e0 + j];
            #pragma unroll
            for (int ii = 0; ii < 8; ii++) {
                float xv = xs[rr][i0 + ii];
                #pragma unroll
                for (int j = 0; j < 4; j++) acc[ii][j] += xv * wv[j];
            }
        }
        __syncthreads();
    }
    #pragma unroll
    for (int ii = 0; ii < 8; ii++)
        #pragma unroll
        for (int j = 0; j < 4; j++)
            atomicAdd(&g_attr_part[(i0+ii)*EMB + e0 + j], acc[ii][j]);
}

__global__ __launch_bounds__(256) void k_attr2(const float* __restrict__ b1,
                                               const float* __restrict__ W2,
                                               const float* __restrict__ b2) {
    __shared__ float xa1[IN_DIMS*EMB];
    __shared__ float W2s[EMB*HID];
    int t = threadIdx.x;
    for (int i = t; i < IN_DIMS*EMB; i += 256)
        xa1[i] = fmaxf(g_attr_part[i] + b1[i % EMB], 0.f);
    for (int i = t; i < EMB*HID; i += 256) W2s[i] = W2[i];
    __syncthreads();
    int i0 = (t >> 4) * 8;
    int h0 = (t & 15) * 4;
    float acc[8][4];
    #pragma unroll
    for (int a = 0; a < 8; a++)
        #pragma unroll
        for (int b = 0; b < 4; b++) acc[a][b] = 0.f;
    for (int k = 0; k < EMB; k++) {
        float wv[4];
        #pragma unroll
        for (int j = 0; j < 4; j++) wv[j] = W2s[k*HID + h0 + j];
        #pragma unroll
        for (int ii = 0; ii < 8; ii++) {
            float xv = xa1[(i0+ii)*EMB + k];
            #pragma unroll
            for (int j = 0; j < 4; j++) acc[ii][j] += xv * wv[j];
        }
    }
    #pragma unroll
    for (int ii = 0; ii < 8; ii++)
        #pragma unroll
        for (int j = 0; j < 4; j++)
            g_xa2[(i0+ii)*HID + h0 + j] = acc[ii][j] + b2[h0 + j];
}

__global__ __launch_bounds__(256) void k_xout(float* __restrict__ out) {
    __shared__ float xa[IN_DIMS*(HID+1)];
    __shared__ float es[32*HID];
    int t = threadIdx.x;
    for (int i = t; i < IN_DIMS*HID; i += 256) {
        int r = i / HID, c = i % HID;
        xa[r*(HID+1) + c] = g_xa2[i];
    }
    int nb = blockIdx.x * 32;
    for (int i = t; i < 32*HID; i += 256) es[i] = g_embP[(size_t)nb*HID + i];
    __syncthreads();
    int nl = t >> 3;
    int ib = (t & 7) * 16;
    const float* e = &es[nl*HID];
    int n = nb + nl;
    if (n >= N_NODES) return;
    for (int ii = 0; ii < 16; ii++) {
        int i = ib + ii;
        const float* w = &xa[i*(HID+1)];
        float acc = 0.f;
        #pragma unroll 8
        for (int k = 0; k < HID; k++) acc += e[k]*w[k];
        out[(size_t)n*IN_DIMS + i] = acc;
    }
}

// ===== s_ GEMM: 2-pass fp16 split (hi*hi + lo*hi), fp32 acc (R8 config) =====
#define ROWB 272
#define BOFF 34816
#define SMEM_S (2*34816)
#define TRS 132

__device__ __forceinline__ uint32_t smem_u32(const void* p) {
    uint32_t a;
    asm("{ .reg .u64 t; cvta.to.shared.u64 t, %1; cvt.u32.u64 %0, t; }" : "=r"(a) : "l"(p));
    return a;
}
__device__ __forceinline__ void ldsm4(uint32_t addr, uint32_t& r0, uint32_t& r1,
                                      uint32_t& r2, uint32_t& r3) {
    asm volatile("ldmatrix.sync.aligned.m8n8.x4.shared.b16 {%0,%1,%2,%3}, [%4];"
                 : "=r"(r0), "=r"(r1), "=r"(r2), "=r"(r3) : "r"(addr));
}
__device__ __forceinline__ void mma_f32(float c[4], uint32_t a0, uint32_t a1,
                                        uint32_t a2, uint32_t a3,
                                        uint32_t b0, uint32_t b1) {
    asm volatile(
        "mma.sync.aligned.m16n8k16.row.col.f32.f16.f16.f32 "
        "{%0,%1,%2,%3}, {%4,%5,%6,%7}, {%8,%9}, {%0,%1,%2,%3};"
        : "+f"(c[0]), "+f"(c[1]), "+f"(c[2]), "+f"(c[3])
        : "r"(a0), "r"(a1), "r"(a2), "r"(a3), "r"(b0), "r"(b1));
}

extern __shared__ char smem_s[];

__global__ __launch_bounds__(256) void k_s_mma(float* __restrict__ sout) {
    int b = blockIdx.x;
    int ti = 0;
    {
        int rem = b, rowlen = NT;
        while (rem >= rowlen) { rem -= rowlen; ti++; rowlen--; }
        b = rem;
    }
    int tj = ti + b;

    int t = threadIdx.x;
    int warp = t >> 5, lane = t & 31;
    int wm = warp >> 1, wn = warp & 1;
    int g = lane >> 2, tq = lane & 3;
    int q = lane >> 3, r8 = lane & 7;

    const __half* gA = &g_Ehf[(size_t)ti * TILE * KS];
    const __half* gB = &g_Ehf[(size_t)tj * TILE * KS];
    #pragma unroll
    for (int i = 0; i < 8; i++) {
        int v = i * 256 + t;
        int row = v >> 4;
        int c16 = v & 15;
        *(float4*)(smem_s + row*ROWB + c16*16) = *(const float4*)(gA + row*KS + c16*8);
    }
    #pragma unroll
    for (int i = 0; i < 4; i++) {
        int v = i * 256 + t;
        int row = v >> 3;
        int c8 = v & 7;
        *(float4*)(smem_s + BOFF + row*ROWB + c8*16) = *(const float4*)(gB + row*KS + c8*8);
    }
    __syncthreads();

    uint32_t sA = smem_u32(smem_s);
    uint32_t sB = sA + BOFF;

    uint32_t aAddr[2], bAddr[4];
    #pragma unroll
    for (int mt = 0; mt < 2; mt++)
        aAddr[mt] = sA + (uint32_t)(wm*32 + mt*16 + r8 + (q & 1)*8)*ROWB + (uint32_t)((q >> 1)*8)*2;
    #pragma unroll
    for (int n2 = 0; n2 < 4; n2++)
        bAddr[n2] = sB + (uint32_t)(wn*64 + n2*16 + r8 + (q >> 1)*8)*ROWB + (uint32_t)((q & 1)*8)*2;

    float c[2][8][4];
    #pragma unroll
    for (int mt = 0; mt < 2; mt++)
        #pragma unroll
        for (int nt = 0; nt < 8; nt++)
            #pragma unroll
            for (int rr = 0; rr < 4; rr++) c[mt][nt][rr] = 0.f;

    #pragma unroll
    for (int kk = 0; kk < 4; kk++) {
        uint32_t ka = (uint32_t)kk * 32;
        uint32_t ah[2][4], al[2][4];
        #pragma unroll
        for (int mt = 0; mt < 2; mt++) {
            ldsm4(aAddr[mt] + ka,       ah[mt][0], ah[mt][1], ah[mt][2], ah[mt][3]);
            ldsm4(aAddr[mt] + 128 + ka, al[mt][0], al[mt][1], al[mt][2], al[mt][3]);
        }
        #pragma unroll
        for (int n2 = 0; n2 < 4; n2++) {
            uint32_t b0, b1, b2, b3;
            ldsm4(bAddr[n2] + ka, b0, b1, b2, b3);
            int nt = n2 * 2;
            mma_f32(c[0][nt],   ah[0][0], ah[0][1], ah[0][2], ah[0][3], b0, b1);
            mma_f32(c[1][nt],   ah[1][0], ah[1][1], ah[1][2], ah[1][3], b0, b1);
            mma_f32(c[0][nt+1], ah[0][0], ah[0][1], ah[0][2], ah[0][3], b2, b3);
            mma_f32(c[1][nt+1], ah[1][0], ah[1][1], ah[1][2], ah[1][3], b2, b3);
            mma_f32(c[0][nt],   al[0][0], al[0][1], al[0][2], al[0][3], b0, b1);
            mma_f32(c[1][nt],   al[1][0], al[1][1], al[1][2], al[1][3], b0, b1);
            mma_f32(c[0][nt+1], al[0][0], al[0][1], al[0][2], al[0][3], b2, b3);
            mma_f32(c[1][nt+1], al[1][0], al[1][1], al[1][2], al[1][3], b2, b3);
        }
    }

    #pragma unroll
    for (int mt = 0; mt < 2; mt++)
        #pragma unroll
        for (int nt = 0; nt < 8; nt++)
            #pragma unroll
            for (int rr = 0; rr < 4; rr++)
                c[mt][nt][rr] = 1.f / (1.f + __expf(-c[mt][nt][rr]));

    #pragma unroll
    for (int mt = 0; mt < 2; mt++) {
        #pragma unroll
        for (int rr = 0; rr < 2; rr++) {
            int gr = ti*TILE + wm*32 + mt*16 + g + rr*8;
            if (gr >= N_NODES) continue;
            size_t obase = (size_t)gr * N_NODES;
            #pragma unroll
            for (int nt = 0; nt < 8; nt++) {
                int gc = tj*TILE + wn*64 + nt*8 + tq*2;
                if (gc < N_NODES)
                    *(float2*)&sout[obase + gc] =
                        make_float2(c[mt][nt][rr*2], c[mt][nt][rr*2 + 1]);
            }
        }
    }

    if (ti != tj) {
        __syncthreads();
        float* tr = (float*)smem_s;
        #pragma unroll
        for (int mt = 0; mt < 2; mt++) {
            #pragma unroll
            for (int rr = 0; rr < 2; rr++) {
                int lr = wm*32 + mt*16 + g + rr*8;
                #pragma unroll
                for (int nt = 0; nt < 8; nt++) {
                    int lc = wn*64 + nt*8 + tq*2;
                    tr[lc*TRS + lr]     = c[mt][nt][rr*2];
                    tr[(lc+1)*TRS + lr] = c[mt][nt][rr*2 + 1];
                }
            }
        }
        __syncthreads();
        int len = N_NODES - ti*TILE;
        if (len > TILE) len = TILE;
        int lr0 = lane * 4;
        #pragma unroll
        for (int rr2 = 0; rr2 < 16; rr2++) {
            int lc = warp*16 + rr2;
            int gcRow = tj*TILE + lc;
            if (gcRow < N_NODES && lr0 < len) {
                *(float4*)&sout[(size_t)gcRow*N_NODES + ti*TILE + lr0] =
                    *(float4*)&tr[lc*TRS + lr0];
            }
        }
    }
}

// ---------------- launch ----------------
extern "C" void kernel_launch(void* const* d_in, const int* in_sizes, int n_in,
                              void* d_out, int out_size) {
    const float* x       = (const float*)d_in[0];
    const int*   ei      = (const int*)d_in[1];
    const float* W_stru  = (const float*)d_in[3];
    const float* b_stru  = (const float*)d_in[4];
    const float* W_gat   = (const float*)d_in[5];
    const float* att_src = (const float*)d_in[6];
    const float* att_dst = (const float*)d_in[7];
    const float* b_gat   = (const float*)d_in[8];
    const float* W_attr1 = (const float*)d_in[9];
    const float* b_attr1 = (const float*)d_in[10];
    const float* W_attr2 = (const float*)d_in[11];
    const float* b_attr2 = (const float*)d_in[12];

    int E = in_sizes[1] / 2;
    int EN = E + N_NODES;

    float* out   = (float*)d_out;
    float* x_out = out;
    float* s_out = out + (size_t)N_NODES * IN_DIMS;

    cudaFuncSetAttribute(k_enc, cudaFuncAttributeMaxDynamicSharedMemorySize, 73728);
    cudaFuncSetAttribute(k_s_mma, cudaFuncAttributeMaxDynamicSharedMemorySize, SMEM_S);

    // order: launch #4 (ncu capture slot) = k_enc
    k_azero <<<(IN_DIMS*EMB + 255) / 256, 256>>>();
    k_edge1 <<<(EN + 255) / 256, 256>>>(ei, E);
    k_scan  <<<1, 1024>>>();
    k_enc   <<<(N_NODES + 31) / 32, 256, 73728>>>(x, W_stru, b_stru, W_gat, att_src, att_dst);
    k_edge2 <<<(EN + 255) / 256, 256>>>(ei, E);
    k_aggr  <<<(N_NODES * 32 + 255) / 256, 256>>>(b_gat);
    k_attr1 <<<100, 256>>>(x, W_attr1);
    k_attr2 <<<1, 256>>>(b_attr1, W_attr2, b_attr2);
    k_xout  <<<(N_NODES + 31) / 32, 256>>>(x_out);
    k_s_mma <<<NT * (NT + 1) / 2, 256, SMEM_S>>>(s_out);
}

// round 11
// speedup vs baseline: 1.0898x; 1.0230x over previous
#include <cuda_runtime.h>
#include <cuda_fp16.h>
#include <math.h>
#include <stdint.h>

#define N_NODES 10000
#define IN_DIMS 128
#define EMB 64
#define HID 64
#define NEG_SLOPE 0.2f
#define TILE 128
#define NT 79                 // ceil(N/128)
#define NPAD (NT*TILE)        // 10112
#define MAXEDGE 400000
#define KS 128                // [hi(64) | lo(64)] fp16 split rows

// ---------------- scratch (no allocations allowed) ----------------
__device__ float    g_hp[N_NODES*HID];
__device__ float    g_asrc[N_NODES];
__device__ float    g_adst[N_NODES];
__device__ float    g_embP[N_NODES*HID];
__device__ float    g_attr_part[IN_DIMS*EMB];
__device__ float    g_xa2[IN_DIMS*HID];
__device__ __align__(16) __half g_Ehf[NPAD*KS];
__device__ int g_deg[N_NODES];
__device__ int g_off[N_NODES + 1];
__device__ int g_pos[N_NODES];
__device__ int2 g_epack[MAXEDGE + N_NODES];

// ===== zero attr_part =====
__global__ void k_azero() {
    int i = blockIdx.x * blockDim.x + threadIdx.x;
    if (i < IN_DIMS*EMB) g_attr_part[i] = 0.f;
}

// ===== degree count =====
__global__ void k_edge1(const int* __restrict__ ei, int E) {
    int i = blockIdx.x * blockDim.x + threadIdx.x;
    if (i >= E + N_NODES) return;
    int d = (i < E) ? ei[E + i] : (i - E);
    atomicAdd(&g_deg[d], 1);
}

// ===== 3-barrier block scan; writes off+pos; self-cleans deg =====
__global__ __launch_bounds__(1024) void k_scan() {
    __shared__ int wsum[32];
    int t = threadIdx.x, lane = t & 31, wid = t >> 5;
    int base = t * 10;
    int v[10];
    int tot = 0;
    #pragma unroll
    for (int j = 0; j < 10; j++) {
        int idx = base + j;
        v[j] = (idx < N_NODES) ? g_deg[idx] : 0;
        tot += v[j];
    }
    int s = tot;
    #pragma unroll
    for (int o = 1; o < 32; o <<= 1) {
        int nv = __shfl_up_sync(0xffffffffu, s, o);
        if (lane >= o) s += nv;
    }
    if (lane == 31) wsum[wid] = s;
    __syncthreads();
    if (wid == 0) {
        int ws = wsum[lane];
        #pragma unroll
        for (int o = 1; o < 32; o <<= 1) {
            int nv = __shfl_up_sync(0xffffffffu, ws, o);
            if (lane >= o) ws += nv;
        }
        wsum[lane] = ws;
    }
    __syncthreads();
    int wex = wid ? wsum[wid - 1] : 0;
    int run = wex + s - tot;
    #pragma unroll
    for (int j = 0; j < 10; j++) {
        int idx = base + j;
        if (idx < N_NODES) {
            g_off[idx] = run;
            g_pos[idx] = run;
            g_deg[idx] = 0;
            run += v[j];
            if (idx == N_NODES - 1) g_off[N_NODES] = run;
        }
    }
}

// ===== fused encoder, 512 thr / 64 nodes per block =====
extern __shared__ float s_enc[];
__global__ __launch_bounds__(512) void k_enc(const float* __restrict__ x,
                                             const float* __restrict__ W1,
                                             const float* __restrict__ b1,
                                             const float* __restrict__ W2,
                                             const float* __restrict__ att_s,
                                             const float* __restrict__ att_d) {
    float* Ws1 = s_enc;            //  8192 floats
    float* Ws2 = s_enc + 8192;     //  4096
    float* xs  = s_enc + 12288;    //  8192 (64 x 128)
    float* hs  = s_enc + 20480;    //  4096 (64 x 64)
    __shared__ float As[HID], Ad[HID], Bs1[EMB];

    int t = threadIdx.x;
    int nbase = blockIdx.x * 64;

    #pragma unroll
    for (int i = 0; i < 4; i++)
        ((float4*)Ws1)[t + i*512] = ((const float4*)W1)[t + i*512];
    #pragma unroll
    for (int i = 0; i < 2; i++)
        ((float4*)Ws2)[t + i*512] = ((const float4*)W2)[t + i*512];
    #pragma unroll
    for (int i = 0; i < 4; i++) {
        int v = t + i*512;                 // 0..2047 float4 in block tile
        int n = nbase + (v >> 5);
        ((float4*)xs)[v] = (n < N_NODES)
            ? ((const float4*)x)[(size_t)nbase*32 + v] : make_float4(0,0,0,0);
    }
    if (t < HID) { As[t] = att_s[t]; Ad[t] = att_d[t]; }
    else if (t < 128) { Bs1[t - HID] = b1[t - HID]; }
    __syncthreads();

    int nl = t >> 4;          // 0..31
    int e0 = (t & 15) * 4;

    #pragma unroll
    for (int it = 0; it < 2; it++) {
        int row = nl + it*32;
        float a0=0.f, a1=0.f, a2=0.f, a3=0.f;
        const float* xr = &xs[row*IN_DIMS];
        #pragma unroll 4
        for (int k = 0; k < IN_DIMS; k++) {
            float xv = xr[k];
            float4 w = *(const float4*)&Ws1[k*EMB + e0];
            a0 += xv*w.x; a1 += xv*w.y; a2 += xv*w.z; a3 += xv*w.w;
        }
        *(float4*)&hs[row*EMB + e0] = make_float4(
            fmaxf(a0 + Bs1[e0+0], 0.f), fmaxf(a1 + Bs1[e0+1], 0.f),
            fmaxf(a2 + Bs1[e0+2], 0.f), fmaxf(a3 + Bs1[e0+3], 0.f));
    }
    __syncthreads();

    #pragma unroll
    for (int it = 0; it < 2; it++) {
        int row = nl + it*32;
        int n = nbase + row;
        float a0=0.f, a1=0.f, a2=0.f, a3=0.f;
        const float* hr = &hs[row*EMB];
        #pragma unroll 8
        for (int k = 0; k < EMB; k++) {
            float hv = hr[k];
            float4 w = *(const float4*)&Ws2[k*HID + e0];
            a0 += hv*w.x; a1 += hv*w.y; a2 += hv*w.z; a3 += hv*w.w;
        }
        if (n < N_NODES)
            *(float4*)&g_hp[(size_t)n*HID + e0] = make_float4(a0, a1, a2, a3);
        float ps = a0*As[e0] + a1*As[e0+1] + a2*As[e0+2] + a3*As[e0+3];
        float pd = a0*Ad[e0] + a1*Ad[e0+1] + a2*Ad[e0+2] + a3*Ad[e0+3];
        #pragma unroll
        for (int o = 8; o; o >>= 1) {
            ps += __shfl_down_sync(0xffffffffu, ps, o, 16);
            pd += __shfl_down_sync(0xffffffffu, pd, o, 16);
        }
        if ((t & 15) == 0 && n < N_NODES) { g_asrc[n] = ps; g_adst[n] = pd; }
    }
}

// ===== weight + scatter into CSR slots =====
__global__ void k_edge2(const int* __restrict__ ei, int E) {
    int i = blockIdx.x * blockDim.x + threadIdx.x;
    if (i >= E + N_NODES) return;
    int s, d;
    if (i < E) { s = ei[i]; d = ei[E + i]; } else { s = d = i - E; }
    float e = g_asrc[s] + g_adst[d];
    e = (e > 0.f) ? e : NEG_SLOPE * e;
    float w = __expf(e);
    int pos = atomicAdd(&g_pos[d], 1);
    g_epack[pos] = make_int2(s, __float_as_int(w));
}

// ===== warp per dst, 4x unrolled gathers, bias + fp16 split =====
__global__ void k_aggr(const float* __restrict__ bg) {
    int d = (blockIdx.x * blockDim.x + threadIdx.x) >> 5;
    int lane = threadIdx.x & 31;
    if (d >= N_NODES) return;
    int beg = g_off[d], end = g_off[d + 1];
    float wsum = 0.f, a0 = 0.f, a1 = 0.f;
    int p = beg;
    for (; p + 4 <= end; p += 4) {
        int2 e0 = g_epack[p];
        int2 e1 = g_epack[p+1];
        int2 e2 = g_epack[p+2];
        int2 e3 = g_epack[p+3];
        const float* r0 = &g_hp[(size_t)e0.x * HID];
        const float* r1 = &g_hp[(size_t)e1.x * HID];
        const float* r2 = &g_hp[(size_t)e2.x * HID];
        const float* r3 = &g_hp[(size_t)e3.x * HID];
        float h00 = r0[lane],    h01 = r0[32+lane];
        float h10 = r1[lane],    h11 = r1[32+lane];
        float h20 = r2[lane],    h21 = r2[32+lane];
        float h30 = r3[lane],    h31 = r3[32+lane];
        float w0 = __int_as_float(e0.y);
        float w1 = __int_as_float(e1.y);
        float w2 = __int_as_float(e2.y);
        float w3 = __int_as_float(e3.y);
        wsum += (w0 + w1) + (w2 + w3);
        a0 += h00*w0 + h10*w1 + h20*w2 + h30*w3;
        a1 += h01*w0 + h11*w1 + h21*w2 + h31*w3;
    }
    for (; p < end; p++) {
        int2 pk = g_epack[p];
        float w = __int_as_float(pk.y);
        const float* r = &g_hp[(size_t)pk.x * HID];
        wsum += w;
        a0 += r[lane] * w;
        a1 += r[32+lane] * w;
    }
    float inv = 1.f / wsum;
    float v0 = a0 * inv + bg[lane];
    float v1 = a1 * inv + bg[lane + 32];
    g_embP[(size_t)d*HID + lane]      = v0;
    g_embP[(size_t)d*HID + 32 + lane] = v1;
    __half h0 = __float2half(v0);
    __half l0 = __float2half(v0 - __half2float(h0));
    __half h1 = __float2half(v1);
    __half l1 = __float2half(v1 - __half2float(h1));
    size_t eb = (size_t)d * KS;
    g_Ehf[eb + lane]      = h0;
    g_Ehf[eb + 32 + lane] = h1;
    g_Ehf[eb + 64 + lane] = l0;
    g_Ehf[eb + 96 + lane] = l1;
}

__global__ __launch_bounds__(256) void k_attr1(const float* __restrict__ x,
                                               const float* __restrict__ W1) {
    __shared__ float xs[10][IN_DIMS];
    __shared__ float ws[10][EMB];
    int t = threadIdx.x;
    int i0 = (t >> 4) * 8;
    int e0 = (t & 15) * 4;
    float acc[8][4];
    #pragma unroll
    for (int a = 0; a < 8; a++)
        #pragma unroll
        for (int b = 0; b < 4; b++) acc[a][b] = 0.f;
    int rbase = blockIdx.x * 100;
    for (int c = 0; c < 10; c++) {
        for (int i = t; i < 10*IN_DIMS; i += 256) {
            int r = rbase + c*10 + i / IN_DIMS;
            xs[i / IN_DIMS][i % IN_DIMS] = x[(size_t)r*IN_DIMS + (i % IN_DIMS)];
        }
        for (int i = t; i < 10*EMB; i += 256) {
            int r = rbase + c*10 + i / EMB;
            ws[i / EMB][i % EMB] = W1[(size_t)r*EMB + (i % EMB)];
        }
        __syncthreads();
        #pragma unroll
        for (int rr = 0; rr < 10; rr++) {
            float wv[4];
            #pragma unroll
            for (int j = 0; j < 4; j++) wv[j] = ws[rr][e0 + j];
            #pragma unroll
            for (int ii = 0; ii < 8; ii++) {
                float xv = xs[rr][i0 + ii];
                #pragma unroll
                for (int j = 0; j < 4; j++) acc[ii][j] += xv * wv[j];
            }
        }
        __syncthreads();
    }
    #pragma unroll
    for (int ii = 0; ii < 8; ii++)
        #pragma unroll
        for (int j = 0; j < 4; j++)
            atomicAdd(&g_attr_part[(i0+ii)*EMB + e0 + j], acc[ii][j]);
}

__global__ __launch_bounds__(256) void k_attr2(const float* __restrict__ b1,
                                               const float* __restrict__ W2,
                                               const float* __restrict__ b2) {
    __shared__ float xa1[IN_DIMS*EMB];
    __shared__ float W2s[EMB*HID];
    int t = threadIdx.x;
    for (int i = t; i < IN_DIMS*EMB; i += 256)
        xa1[i] = fmaxf(g_attr_part[i] + b1[i % EMB], 0.f);
    for (int i = t; i < EMB*HID; i += 256) W2s[i] = W2[i];
    __syncthreads();
    int i0 = (t >> 4) * 8;
    int h0 = (t & 15) * 4;
    float acc[8][4];
    #pragma unroll
    for (int a = 0; a < 8; a++)
        #pragma unroll
        for (int b = 0; b < 4; b++) acc[a][b] = 0.f;
    for (int k = 0; k < EMB; k++) {
        float wv[4];
        #pragma unroll
        for (int j = 0; j < 4; j++) wv[j] = W2s[k*HID + h0 + j];
        #pragma unroll
        for (int ii = 0; ii < 8; ii++) {
            float xv = xa1[(i0+ii)*EMB + k];
            #pragma unroll
            for (int j = 0; j < 4; j++) acc[ii][j] += xv * wv[j];
        }
    }
    #pragma unroll
    for (int ii = 0; ii < 8; ii++)
        #pragma unroll
        for (int j = 0; j < 4; j++)
            g_xa2[(i0+ii)*HID + h0 + j] = acc[ii][j] + b2[h0 + j];
}

__global__ __launch_bounds__(256) void k_xout(float* __restrict__ out) {
    __shared__ float xa[IN_DIMS*(HID+1)];
    __shared__ float es[32*HID];
    int t = threadIdx.x;
    for (int i = t; i < IN_DIMS*HID; i += 256) {
        int r = i / HID, c = i % HID;
        xa[r*(HID+1) + c] = g_xa2[i];
    }
    int nb = blockIdx.x * 32;
    for (int i = t; i < 32*HID; i += 256) es[i] = g_embP[(size_t)nb*HID + i];
    __syncthreads();
    int nl = t >> 3;
    int ib = (t & 7) * 16;
    const float* e = &es[nl*HID];
    int n = nb + nl;
    if (n >= N_NODES) return;
    for (int ii = 0; ii < 16; ii++) {
        int i = ib + ii;
        const float* w = &xa[i*(HID+1)];
        float acc = 0.f;
        #pragma unroll 8
        for (int k = 0; k < HID; k++) acc += e[k]*w[k];
        out[(size_t)n*IN_DIMS + i] = acc;
    }
}

// ===== s_ GEMM: 512 thr, 16 warps (16x64 warp tile), 2-pass fp16 split =====
#define ROWB 272              // A row stride (bytes)
#define ROWB_B 144            // B row stride (bytes, hi-only)
#define BOFF 34816            // 128*272
#define SMEM_S 69632          // covers tiles (53KB) and the transpose stage (67.5KB)
#define TRS 132

__device__ __forceinline__ uint32_t smem_u32(const void* p) {
    uint32_t a;
    asm("{ .reg .u64 t; cvta.to.shared.u64 t, %1; cvt.u32.u64 %0, t; }" : "=r"(a) : "l"(p));
    return a;
}
__device__ __forceinline__ void ldsm4(uint32_t addr, uint32_t& r0, uint32_t& r1,
                                      uint32_t& r2, uint32_t& r3) {
    asm volatile("ldmatrix.sync.aligned.m8n8.x4.shared.b16 {%0,%1,%2,%3}, [%4];"
                 : "=r"(r0), "=r"(r1), "=r"(r2), "=r"(r3) : "r"(addr));
}
__device__ __forceinline__ void mma_f32(float c[4], uint32_t a0, uint32_t a1,
                                        uint32_t a2, uint32_t a3,
                                        uint32_t b0, uint32_t b1) {
    asm volatile(
        "mma.sync.aligned.m16n8k16.row.col.f32.f16.f16.f32 "
        "{%0,%1,%2,%3}, {%4,%5,%6,%7}, {%8,%9}, {%0,%1,%2,%3};"
        : "+f"(c[0]), "+f"(c[1]), "+f"(c[2]), "+f"(c[3])
        : "r"(a0), "r"(a1), "r"(a2), "r"(a3), "r"(b0), "r"(b1));
}

extern __shared__ char smem_s[];

__global__ __launch_bounds__(512, 2) void k_s_mma(float* __restrict__ sout) {
    int b = blockIdx.x;
    int ti = 0;
    {
        int rem = b, rowlen = NT;
        while (rem >= rowlen) { rem -= rowlen; ti++; rowlen--; }
        b = rem;
    }
    int tj = ti + b;

    int t = threadIdx.x;
    int warp = t >> 5, lane = t & 31;
    int wm = warp >> 1, wn = warp & 1;     // 8x2 warps: 16x64 warp tile
    int g = lane >> 2, tq = lane & 3;
    int q = lane >> 3, r8 = lane & 7;

    const __half* gA = &g_Ehf[(size_t)ti * TILE * KS];
    const __half* gB = &g_Ehf[(size_t)tj * TILE * KS];
    // A: 2048 float4 slots ([hi|lo] rows)
    #pragma unroll
    for (int i = 0; i < 4; i++) {
        int v = i * 512 + t;
        int row = v >> 4;
        int c16 = v & 15;
        *(float4*)(smem_s + row*ROWB + c16*16) = *(const float4*)(gA + row*KS + c16*8);
    }
    // B: 1024 float4 slots (hi half only)
    #pragma unroll
    for (int i = 0; i < 2; i++) {
        int v = i * 512 + t;
        int row = v >> 3;
        int c8 = v & 7;
        *(float4*)(smem_s + BOFF + row*ROWB_B + c8*16) = *(const float4*)(gB + row*KS + c8*8);
    }
    __syncthreads();

    uint32_t sA = smem_u32(smem_s);
    uint32_t sB = sA + BOFF;

    uint32_t aAddr = sA + (uint32_t)(wm*16 + r8 + (q & 1)*8)*ROWB + (uint32_t)((q >> 1)*8)*2;
    uint32_t bAddr[4];
    #pragma unroll
    for (int n2 = 0; n2 < 4; n2++)
        bAddr[n2] = sB + (uint32_t)(wn*64 + n2*16 + r8 + (q >> 1)*8)*ROWB_B + (uint32_t)((q & 1)*8)*2;

    float c[8][4];
    #pragma unroll
    for (int nt = 0; nt < 8; nt++)
        #pragma unroll
        for (int rr = 0; rr < 4; rr++) c[nt][rr] = 0.f;

    #pragma unroll
    for (int kk = 0; kk < 4; kk++) {
        uint32_t ka = (uint32_t)kk * 32;
        uint32_t ah[4], al[4];
        ldsm4(aAddr + ka,       ah[0], ah[1], ah[2], ah[3]);
        ldsm4(aAddr + 128 + ka, al[0], al[1], al[2], al[3]);
        #pragma unroll
        for (int n2 = 0; n2 < 4; n2++) {
            uint32_t b0, b1, b2, b3;
            ldsm4(bAddr[n2] + ka, b0, b1, b2, b3);
            int nt = n2 * 2;
            mma_f32(c[nt],   ah[0], ah[1], ah[2], ah[3], b0, b1);
            mma_f32(c[nt+1], ah[0], ah[1], ah[2], ah[3], b2, b3);
            mma_f32(c[nt],   al[0], al[1], al[2], al[3], b0, b1);
            mma_f32(c[nt+1], al[0], al[1], al[2], al[3], b2, b3);
        }
    }

    #pragma unroll
    for (int nt = 0; nt < 8; nt++)
        #pragma unroll
        for (int rr = 0; rr < 4; rr++)
            c[nt][rr] = 1.f / (1.f + __expf(-c[nt][rr]));

    // normal tile
    #pragma unroll
    for (int rr = 0; rr < 2; rr++) {
        int gr = ti*TILE + wm*16 + g + rr*8;
        if (gr >= N_NODES) continue;
        size_t obase = (size_t)gr * N_NODES;
        #pragma unroll
        for (int nt = 0; nt < 8; nt++) {
            int gc = tj*TILE + wn*64 + nt*8 + tq*2;
            if (gc < N_NODES)
                *(float2*)&sout[obase + gc] =
                    make_float2(c[nt][rr*2], c[nt][rr*2 + 1]);
        }
    }

    // mirror tile via smem transpose stage
    if (ti != tj) {
        __syncthreads();
        float* tr = (float*)smem_s;
        #pragma unroll
        for (int rr = 0; rr < 2; rr++) {
            int lr = wm*16 + g + rr*8;
            #pragma unroll
            for (int nt = 0; nt < 8; nt++) {
                int lc = wn*64 + nt*8 + tq*2;
                tr[lc*TRS + lr]     = c[nt][rr*2];
                tr[(lc+1)*TRS + lr] = c[nt][rr*2 + 1];
            }
        }
        __syncthreads();
        int len = N_NODES - ti*TILE;
        if (len > TILE) len = TILE;
        int lr0 = lane * 4;
        #pragma unroll
        for (int rr2 = 0; rr2 < 8; rr2++) {
            int lc = warp*8 + rr2;
            int gcRow = tj*TILE + lc;
            if (gcRow < N_NODES && lr0 < len) {
                *(float4*)&sout[(size_t)gcRow*N_NODES + ti*TILE + lr0] =
                    *(float4*)&tr[lc*TRS + lr0];
            }
        }
    }
}

// ---------------- launch ----------------
extern "C" void kernel_launch(void* const* d_in, const int* in_sizes, int n_in,
                              void* d_out, int out_size) {
    const float* x       = (const float*)d_in[0];
    const int*   ei      = (const int*)d_in[1];
    const float* W_stru  = (const float*)d_in[3];
    const float* b_stru  = (const float*)d_in[4];
    const float* W_gat   = (const float*)d_in[5];
    const float* att_src = (const float*)d_in[6];
    const float* att_dst = (const float*)d_in[7];
    const float* b_gat   = (const float*)d_in[8];
    const float* W_attr1 = (const float*)d_in[9];
    const float* b_attr1 = (const float*)d_in[10];
    const float* W_attr2 = (const float*)d_in[11];
    const float* b_attr2 = (const float*)d_in[12];

    int E = in_sizes[1] / 2;
    int EN = E + N_NODES;

    float* out   = (float*)d_out;
    float* x_out = out;
    float* s_out = out + (size_t)N_NODES * IN_DIMS;

    cudaFuncSetAttribute(k_enc, cudaFuncAttributeMaxDynamicSharedMemorySize, 98304);
    cudaFuncSetAttribute(k_s_mma, cudaFuncAttributeMaxDynamicSharedMemorySize, SMEM_S);

    // order: launch #4 (ncu capture slot) = k_attr1
    k_azero <<<(IN_DIMS*EMB + 255) / 256, 256>>>();
    k_edge1 <<<(EN + 255) / 256, 256>>>(ei, E);
    k_scan  <<<1, 1024>>>();
    k_attr1 <<<100, 256>>>(x, W_attr1);
    k_enc   <<<(N_NODES + 63) / 64, 512, 98304>>>(x, W_stru, b_stru, W_gat, att_src, att_dst);
    k_edge2 <<<(EN + 255) / 256, 256>>>(ei, E);
    k_aggr  <<<(N_NODES * 32 + 255) / 256, 256>>>(b_gat);
    k_attr2 <<<1, 256>>>(b_attr1, W_attr2, b_attr2);
    k_xout  <<<(N_NODES + 31) / 32, 256>>>(x_out);
    k_s_mma <<<NT * (NT + 1) / 2, 512, SMEM_S>>>(s_out);
}

// round 12
// speedup vs baseline: 1.1848x; 1.0872x over previous
#include <cuda_runtime.h>
#include <cuda_fp16.h>
#include <math.h>
#include <stdint.h>

#define N_NODES 10000
#define IN_DIMS 128
#define EMB 64
#define HID 64
#define NEG_SLOPE 0.2f
#define TILE 128
#define NT 79                 // ceil(N/128)
#define NPAD (NT*TILE)        // 10112
#define MAXEDGE 400000
#define KS 128                // [hi(64) | lo(64)] fp16 split rows

// ---------------- scratch (no allocations allowed) ----------------
__device__ float    g_hp[N_NODES*HID];
__device__ float    g_asrc[N_NODES];
__device__ float    g_adst[N_NODES];
__device__ float    g_embP[N_NODES*HID];
__device__ float    g_attr_part[IN_DIMS*EMB];
__device__ float    g_xa2[IN_DIMS*HID];
__device__ __align__(16) __half g_Ehf[NPAD*KS];
__device__ int g_deg[N_NODES];
__device__ int g_off[N_NODES + 1];
__device__ int g_pos[N_NODES];
__device__ int2 g_epack[MAXEDGE + N_NODES];

// ===== degree count (+ zero attr_part for this run) =====
__global__ void k_edge1(const int* __restrict__ ei, int E) {
    int i = blockIdx.x * blockDim.x + threadIdx.x;
    if (i < IN_DIMS*EMB) g_attr_part[i] = 0.f;
    if (i >= E + N_NODES) return;
    int d = (i < E) ? ei[E + i] : (i - E);
    atomicAdd(&g_deg[d], 1);
}

// ===== 3-barrier block scan; writes off+pos; self-cleans deg =====
__global__ __launch_bounds__(1024) void k_scan() {
    __shared__ int wsum[32];
    int t = threadIdx.x, lane = t & 31, wid = t >> 5;
    int base = t * 10;
    int v[10];
    int tot = 0;
    #pragma unroll
    for (int j = 0; j < 10; j++) {
        int idx = base + j;
        v[j] = (idx < N_NODES) ? g_deg[idx] : 0;
        tot += v[j];
    }
    int s = tot;
    #pragma unroll
    for (int o = 1; o < 32; o <<= 1) {
        int nv = __shfl_up_sync(0xffffffffu, s, o);
        if (lane >= o) s += nv;
    }
    if (lane == 31) wsum[wid] = s;
    __syncthreads();
    if (wid == 0) {
        int ws = wsum[lane];
        #pragma unroll
        for (int o = 1; o < 32; o <<= 1) {
            int nv = __shfl_up_sync(0xffffffffu, ws, o);
            if (lane >= o) ws += nv;
        }
        wsum[lane] = ws;
    }
    __syncthreads();
    int wex = wid ? wsum[wid - 1] : 0;
    int run = wex + s - tot;
    #pragma unroll
    for (int j = 0; j < 10; j++) {
        int idx = base + j;
        if (idx < N_NODES) {
            g_off[idx] = run;
            g_pos[idx] = run;
            g_deg[idx] = 0;
            run += v[j];
            if (idx == N_NODES - 1) g_off[N_NODES] = run;
        }
    }
}

// ===== attr1: 250 blocks x 40 rows, single-shot smem load, 1 sync =====
#define A1_ROWS 40
__global__ __launch_bounds__(256) void k_attr1(const float* __restrict__ x,
                                               const float* __restrict__ W1) {
    __shared__ float xs[A1_ROWS*IN_DIMS];   // 20 KB
    __shared__ float ws[A1_ROWS*EMB];       // 10 KB
    int t = threadIdx.x;
    int rbase = blockIdx.x * A1_ROWS;

    // x slice: 40*128 floats = 1280 float4; 5 per thread
    #pragma unroll
    for (int i = 0; i < 5; i++)
        ((float4*)xs)[t + i*256] =
            ((const float4*)x)[(size_t)rbase*32 + t + i*256];
    // W1 slice: 40*64 floats = 640 float4
    #pragma unroll
    for (int i = 0; i < 3; i++) {
        int v = t + i*256;
        if (v < A1_ROWS*EMB/4)
            ((float4*)ws)[v] = ((const float4*)W1)[(size_t)rbase*16 + v];
    }
    __syncthreads();

    int i0 = (t >> 4) * 8;
    int e0 = (t & 15) * 4;
    float acc[8][4];
    #pragma unroll
    for (int a = 0; a < 8; a++)
        #pragma unroll
        for (int b = 0; b < 4; b++) acc[a][b] = 0.f;

    #pragma unroll 4
    for (int rr = 0; rr < A1_ROWS; rr++) {
        float wv[4];
        #pragma unroll
        for (int j = 0; j < 4; j++) wv[j] = ws[rr*EMB + e0 + j];
        #pragma unroll
        for (int ii = 0; ii < 8; ii++) {
            float xv = xs[rr*IN_DIMS + i0 + ii];
            #pragma unroll
            for (int j = 0; j < 4; j++) acc[ii][j] += xv * wv[j];
        }
    }
    #pragma unroll
    for (int ii = 0; ii < 8; ii++)
        #pragma unroll
        for (int j = 0; j < 4; j++)
            atomicAdd(&g_attr_part[(i0+ii)*EMB + e0 + j], acc[ii][j]);
}

// ===== fused encoder, 512 thr / 64 nodes per block =====
extern __shared__ float s_enc[];
__global__ __launch_bounds__(512) void k_enc(const float* __restrict__ x,
                                             const float* __restrict__ W1,
                                             const float* __restrict__ b1,
                                             const float* __restrict__ W2,
                                             const float* __restrict__ att_s,
                                             const float* __restrict__ att_d) {
    float* Ws1 = s_enc;            //  8192 floats
    float* Ws2 = s_enc + 8192;     //  4096
    float* xs  = s_enc + 12288;    //  8192 (64 x 128)
    float* hs  = s_enc + 20480;    //  4096 (64 x 64)
    __shared__ float As[HID], Ad[HID], Bs1[EMB];

    int t = threadIdx.x;
    int nbase = blockIdx.x * 64;

    #pragma unroll
    for (int i = 0; i < 4; i++)
        ((float4*)Ws1)[t + i*512] = ((const float4*)W1)[t + i*512];
    #pragma unroll
    for (int i = 0; i < 2; i++)
        ((float4*)Ws2)[t + i*512] = ((const float4*)W2)[t + i*512];
    #pragma unroll
    for (int i = 0; i < 4; i++) {
        int v = t + i*512;
        int n = nbase + (v >> 5);
        ((float4*)xs)[v] = (n < N_NODES)
            ? ((const float4*)x)[(size_t)nbase*32 + v] : make_float4(0,0,0,0);
    }
    if (t < HID) { As[t] = att_s[t]; Ad[t] = att_d[t]; }
    else if (t < 128) { Bs1[t - HID] = b1[t - HID]; }
    __syncthreads();

    int nl = t >> 4;          // 0..31
    int e0 = (t & 15) * 4;

    #pragma unroll
    for (int it = 0; it < 2; it++) {
        int row = nl + it*32;
        float a0=0.f, a1=0.f, a2=0.f, a3=0.f;
        const float* xr = &xs[row*IN_DIMS];
        #pragma unroll 4
        for (int k = 0; k < IN_DIMS; k++) {
            float xv = xr[k];
            float4 w = *(const float4*)&Ws1[k*EMB + e0];
            a0 += xv*w.x; a1 += xv*w.y; a2 += xv*w.z; a3 += xv*w.w;
        }
        *(float4*)&hs[row*EMB + e0] = make_float4(
            fmaxf(a0 + Bs1[e0+0], 0.f), fmaxf(a1 + Bs1[e0+1], 0.f),
            fmaxf(a2 + Bs1[e0+2], 0.f), fmaxf(a3 + Bs1[e0+3], 0.f));
    }
    __syncthreads();

    #pragma unroll
    for (int it = 0; it < 2; it++) {
        int row = nl + it*32;
        int n = nbase + row;
        float a0=0.f, a1=0.f, a2=0.f, a3=0.f;
        const float* hr = &hs[row*EMB];
        #pragma unroll 8
        for (int k = 0; k < EMB; k++) {
            float hv = hr[k];
            float4 w = *(const float4*)&Ws2[k*HID + e0];
            a0 += hv*w.x; a1 += hv*w.y; a2 += hv*w.z; a3 += hv*w.w;
        }
        if (n < N_NODES)
            *(float4*)&g_hp[(size_t)n*HID + e0] = make_float4(a0, a1, a2, a3);
        float ps = a0*As[e0] + a1*As[e0+1] + a2*As[e0+2] + a3*As[e0+3];
        float pd = a0*Ad[e0] + a1*Ad[e0+1] + a2*Ad[e0+2] + a3*Ad[e0+3];
        #pragma unroll
        for (int o = 8; o; o >>= 1) {
            ps += __shfl_down_sync(0xffffffffu, ps, o, 16);
            pd += __shfl_down_sync(0xffffffffu, pd, o, 16);
        }
        if ((t & 15) == 0 && n < N_NODES) { g_asrc[n] = ps; g_adst[n] = pd; }
    }
}

// ===== weight + scatter into CSR slots =====
__global__ void k_edge2(const int* __restrict__ ei, int E) {
    int i = blockIdx.x * blockDim.x + threadIdx.x;
    if (i >= E + N_NODES) return;
    int s, d;
    if (i < E) { s = ei[i]; d = ei[E + i]; } else { s = d = i - E; }
    float e = g_asrc[s] + g_adst[d];
    e = (e > 0.f) ? e : NEG_SLOPE * e;
    float w = __expf(e);
    int pos = atomicAdd(&g_pos[d], 1);
    g_epack[pos] = make_int2(s, __float_as_int(w));
}

// ===== warp per dst, 4x unrolled gathers, bias + fp16 split =====
__global__ void k_aggr(const float* __restrict__ bg) {
    int d = (blockIdx.x * blockDim.x + threadIdx.x) >> 5;
    int lane = threadIdx.x & 31;
    if (d >= N_NODES) return;
    int beg = g_off[d], end = g_off[d + 1];
    float wsum = 0.f, a0 = 0.f, a1 = 0.f;
    int p = beg;
    for (; p + 4 <= end; p += 4) {
        int2 e0 = g_epack[p];
        int2 e1 = g_epack[p+1];
        int2 e2 = g_epack[p+2];
        int2 e3 = g_epack[p+3];
        const float* r0 = &g_hp[(size_t)e0.x * HID];
        const float* r1 = &g_hp[(size_t)e1.x * HID];
        const float* r2 = &g_hp[(size_t)e2.x * HID];
        const float* r3 = &g_hp[(size_t)e3.x * HID];
        float h00 = r0[lane],    h01 = r0[32+lane];
        float h10 = r1[lane],    h11 = r1[32+lane];
        float h20 = r2[lane],    h21 = r2[32+lane];
        float h30 = r3[lane],    h31 = r3[32+lane];
        float w0 = __int_as_float(e0.y);
        float w1 = __int_as_float(e1.y);
        float w2 = __int_as_float(e2.y);
        float w3 = __int_as_float(e3.y);
        wsum += (w0 + w1) + (w2 + w3);
        a0 += h00*w0 + h10*w1 + h20*w2 + h30*w3;
        a1 += h01*w0 + h11*w1 + h21*w2 + h31*w3;
    }
    for (; p < end; p++) {
        int2 pk = g_epack[p];
        float w = __int_as_float(pk.y);
        const float* r = &g_hp[(size_t)pk.x * HID];
        wsum += w;
        a0 += r[lane] * w;
        a1 += r[32+lane] * w;
    }
    float inv = 1.f / wsum;
    float v0 = a0 * inv + bg[lane];
    float v1 = a1 * inv + bg[lane + 32];
    g_embP[(size_t)d*HID + lane]      = v0;
    g_embP[(size_t)d*HID + 32 + lane] = v1;
    __half h0 = __float2half(v0);
    __half l0 = __float2half(v0 - __half2float(h0));
    __half h1 = __float2half(v1);
    __half l1 = __float2half(v1 - __half2float(h1));
    size_t eb = (size_t)d * KS;
    g_Ehf[eb + lane]      = h0;
    g_Ehf[eb + 32 + lane] = h1;
    g_Ehf[eb + 64 + lane] = l0;
    g_Ehf[eb + 96 + lane] = l1;
}

__global__ __launch_bounds__(256) void k_attr2(const float* __restrict__ b1,
                                               const float* __restrict__ W2,
                                               const float* __restrict__ b2) {
    __shared__ float xa1[IN_DIMS*EMB];
    __shared__ float W2s[EMB*HID];
    int t = threadIdx.x;
    for (int i = t; i < IN_DIMS*EMB; i += 256)
        xa1[i] = fmaxf(g_attr_part[i] + b1[i % EMB], 0.f);
    for (int i = t; i < EMB*HID; i += 256) W2s[i] = W2[i];
    __syncthreads();
    int i0 = (t >> 4) * 8;
    int h0 = (t & 15) * 4;
    float acc[8][4];
    #pragma unroll
    for (int a = 0; a < 8; a++)
        #pragma unroll
        for (int b = 0; b < 4; b++) acc[a][b] = 0.f;
    for (int k = 0; k < EMB; k++) {
        float wv[4];
        #pragma unroll
        for (int j = 0; j < 4; j++) wv[j] = W2s[k*HID + h0 + j];
        #pragma unroll
        for (int ii = 0; ii < 8; ii++) {
            float xv = xa1[(i0+ii)*EMB + k];
            #pragma unroll
            for (int j = 0; j < 4; j++) acc[ii][j] += xv * wv[j];
        }
    }
    #pragma unroll
    for (int ii = 0; ii < 8; ii++)
        #pragma unroll
        for (int j = 0; j < 4; j++)
            g_xa2[(i0+ii)*HID + h0 + j] = acc[ii][j] + b2[h0 + j];
}

__global__ __launch_bounds__(256) void k_xout(float* __restrict__ out) {
    __shared__ float xa[IN_DIMS*(HID+1)];
    __shared__ float es[32*HID];
    int t = threadIdx.x;
    for (int i = t; i < IN_DIMS*HID; i += 256) {
        int r = i / HID, c = i % HID;
        xa[r*(HID+1) + c] = g_xa2[i];
    }
    int nb = blockIdx.x * 32;
    for (int i = t; i < 32*HID; i += 256) es[i] = g_embP[(size_t)nb*HID + i];
    __syncthreads();
    int nl = t >> 3;
    int ib = (t & 7) * 16;
    const float* e = &es[nl*HID];
    int n = nb + nl;
    if (n >= N_NODES) return;
    for (int ii = 0; ii < 16; ii++) {
        int i = ib + ii;
        const float* w = &xa[i*(HID+1)];
        float acc = 0.f;
        #pragma unroll 8
        for (int k = 0; k < HID; k++) acc += e[k]*w[k];
        out[(size_t)n*IN_DIMS + i] = acc;
    }
}

// ===== s_ GEMM: 512 thr, 16 warps (16x64 warp tile), 2-pass fp16 split =====
#define ROWB 272
#define ROWB_B 144
#define BOFF 34816
#define SMEM_S 69632
#define TRS 132

__device__ __forceinline__ uint32_t smem_u32(const void* p) {
    uint32_t a;
    asm("{ .reg .u64 t; cvta.to.shared.u64 t, %1; cvt.u32.u64 %0, t; }" : "=r"(a) : "l"(p));
    return a;
}
__device__ __forceinline__ void ldsm4(uint32_t addr, uint32_t& r0, uint32_t& r1,
                                      uint32_t& r2, uint32_t& r3) {
    asm volatile("ldmatrix.sync.aligned.m8n8.x4.shared.b16 {%0,%1,%2,%3}, [%4];"
                 : "=r"(r0), "=r"(r1), "=r"(r2), "=r"(r3) : "r"(addr));
}
__device__ __forceinline__ void mma_f32(float c[4], uint32_t a0, uint32_t a1,
                                        uint32_t a2, uint32_t a3,
                                        uint32_t b0, uint32_t b1) {
    asm volatile(
        "mma.sync.aligned.m16n8k16.row.col.f32.f16.f16.f32 "
        "{%0,%1,%2,%3}, {%4,%5,%6,%7}, {%8,%9}, {%0,%1,%2,%3};"
        : "+f"(c[0]), "+f"(c[1]), "+f"(c[2]), "+f"(c[3])
        : "r"(a0), "r"(a1), "r"(a2), "r"(a3), "r"(b0), "r"(b1));
}

extern __shared__ char smem_s[];

__global__ __launch_bounds__(512, 2) void k_s_mma(float* __restrict__ sout) {
    int b = blockIdx.x;
    int ti = 0;
    {
        int rem = b, rowlen = NT;
        while (rem >= rowlen) { rem -= rowlen; ti++; rowlen--; }
        b = rem;
    }
    int tj = ti + b;

    int t = threadIdx.x;
    int warp = t >> 5, lane = t & 31;
    int wm = warp >> 1, wn = warp & 1;
    int g = lane >> 2, tq = lane & 3;
    int q = lane >> 3, r8 = lane & 7;

    const __half* gA = &g_Ehf[(size_t)ti * TILE * KS];
    const __half* gB = &g_Ehf[(size_t)tj * TILE * KS];
    #pragma unroll
    for (int i = 0; i < 4; i++) {
        int v = i * 512 + t;
        int row = v >> 4;
        int c16 = v & 15;
        *(float4*)(smem_s + row*ROWB + c16*16) = *(const float4*)(gA + row*KS + c16*8);
    }
    #pragma unroll
    for (int i = 0; i < 2; i++) {
        int v = i * 512 + t;
        int row = v >> 3;
        int c8 = v & 7;
        *(float4*)(smem_s + BOFF + row*ROWB_B + c8*16) = *(const float4*)(gB + row*KS + c8*8);
    }
    __syncthreads();

    uint32_t sA = smem_u32(smem_s);
    uint32_t sB = sA + BOFF;

    uint32_t aAddr = sA + (uint32_t)(wm*16 + r8 + (q & 1)*8)*ROWB + (uint32_t)((q >> 1)*8)*2;
    uint32_t bAddr[4];
    #pragma unroll
    for (int n2 = 0; n2 < 4; n2++)
        bAddr[n2] = sB + (uint32_t)(wn*64 + n2*16 + r8 + (q >> 1)*8)*ROWB_B + (uint32_t)((q & 1)*8)*2;

    float c[8][4];
    #pragma unroll
    for (int nt = 0; nt < 8; nt++)
        #pragma unroll
        for (int rr = 0; rr < 4; rr++) c[nt][rr] = 0.f;

    #pragma unroll
    for (int kk = 0; kk < 4; kk++) {
        uint32_t ka = (uint32_t)kk * 32;
        uint32_t ah[4], al[4];
        ldsm4(aAddr + ka,       ah[0], ah[1], ah[2], ah[3]);
        ldsm4(aAddr + 128 + ka, al[0], al[1], al[2], al[3]);
        #pragma unroll
        for (int n2 = 0; n2 < 4; n2++) {
            uint32_t b0, b1, b2, b3;
            ldsm4(bAddr[n2] + ka, b0, b1, b2, b3);
            int nt = n2 * 2;
            mma_f32(c[nt],   ah[0], ah[1], ah[2], ah[3], b0, b1);
            mma_f32(c[nt+1], ah[0], ah[1], ah[2], ah[3], b2, b3);
            mma_f32(c[nt],   al[0], al[1], al[2], al[3], b0, b1);
            mma_f32(c[nt+1], al[0], al[1], al[2], al[3], b2, b3);
        }
    }

    #pragma unroll
    for (int nt = 0; nt < 8; nt++)
        #pragma unroll
        for (int rr = 0; rr < 4; rr++)
            c[nt][rr] = 1.f / (1.f + __expf(-c[nt][rr]));

    #pragma unroll
    for (int rr = 0; rr < 2; rr++) {
        int gr = ti*TILE + wm*16 + g + rr*8;
        if (gr >= N_NODES) continue;
        size_t obase = (size_t)gr * N_NODES;
        #pragma unroll
        for (int nt = 0; nt < 8; nt++) {
            int gc = tj*TILE + wn*64 + nt*8 + tq*2;
            if (gc < N_NODES)
                *(float2*)&sout[obase + gc] =
                    make_float2(c[nt][rr*2], c[nt][rr*2 + 1]);
        }
    }

    if (ti != tj) {
        __syncthreads();
        float* tr = (float*)smem_s;
        #pragma unroll
        for (int rr = 0; rr < 2; rr++) {
            int lr = wm*16 + g + rr*8;
            #pragma unroll
            for (int nt = 0; nt < 8; nt++) {
                int lc = wn*64 + nt*8 + tq*2;
                tr[lc*TRS + lr]     = c[nt][rr*2];
                tr[(lc+1)*TRS + lr] = c[nt][rr*2 + 1];
            }
        }
        __syncthreads();
        int len = N_NODES - ti*TILE;
        if (len > TILE) len = TILE;
        int lr0 = lane * 4;
        #pragma unroll
        for (int rr2 = 0; rr2 < 8; rr2++) {
            int lc = warp*8 + rr2;
            int gcRow = tj*TILE + lc;
            if (gcRow < N_NODES && lr0 < len) {
                *(float4*)&sout[(size_t)gcRow*N_NODES + ti*TILE + lr0] =
                    *(float4*)&tr[lc*TRS + lr0];
            }
        }
    }
}

// ---------------- launch ----------------
extern "C" void kernel_launch(void* const* d_in, const int* in_sizes, int n_in,
                              void* d_out, int out_size) {
    const float* x       = (const float*)d_in[0];
    const int*   ei      = (const int*)d_in[1];
    const float* W_stru  = (const float*)d_in[3];
    const float* b_stru  = (const float*)d_in[4];
    const float* W_gat   = (const float*)d_in[5];
    const float* att_src = (const float*)d_in[6];
    const float* att_dst = (const float*)d_in[7];
    const float* b_gat   = (const float*)d_in[8];
    const float* W_attr1 = (const float*)d_in[9];
    const float* b_attr1 = (const float*)d_in[10];
    const float* W_attr2 = (const float*)d_in[11];
    const float* b_attr2 = (const float*)d_in[12];

    int E = in_sizes[1] / 2;
    int EN = E + N_NODES;

    float* out   = (float*)d_out;
    float* x_out = out;
    float* s_out = out + (size_t)N_NODES * IN_DIMS;

    cudaFuncSetAttribute(k_enc, cudaFuncAttributeMaxDynamicSharedMemorySize, 98304);
    cudaFuncSetAttribute(k_s_mma, cudaFuncAttributeMaxDynamicSharedMemorySize, SMEM_S);

    // order: launch #4 (ncu capture slot) = k_enc (verify 512-thr version)
    k_edge1 <<<(EN + 255) / 256, 256>>>(ei, E);
    k_scan  <<<1, 1024>>>();
    k_attr1 <<<N_NODES / A1_ROWS, 256>>>(x, W_attr1);
    k_enc   <<<(N_NODES + 63) / 64, 512, 98304>>>(x, W_stru, b_stru, W_gat, att_src, att_dst);
    k_edge2 <<<(EN + 255) / 256, 256>>>(ei, E);
    k_aggr  <<<(N_NODES * 32 + 255) / 256, 256>>>(b_gat);
    k_attr2 <<<1, 256>>>(b_attr1, W_attr2, b_attr2);
    k_xout  <<<(N_NODES + 31) / 32, 256>>>(x_out);
    k_s_mma <<<NT * (NT + 1) / 2, 512, SMEM_S>>>(s_out);
}

// round 13
// speedup vs baseline: 1.1858x; 1.0008x over previous
#include <cuda_runtime.h>
#include <cuda_fp16.h>
#include <math.h>
#include <stdint.h>

#define N_NODES 10000
#define IN_DIMS 128
#define EMB 64
#define HID 64
#define NEG_SLOPE 0.2f
#define TILE 128
#define NT 79                 // ceil(N/128)
#define NPAD (NT*TILE)        // 10112
#define MAXEDGE 400000
#define KS 128                // [hi(64) | lo(64)] fp16 split rows

// ---------------- scratch (no allocations allowed) ----------------
__device__ float    g_hp[N_NODES*HID];
__device__ float    g_asrc[N_NODES];
__device__ float    g_adst[N_NODES];
__device__ float    g_embP[N_NODES*HID];
__device__ float    g_attr_part[IN_DIMS*EMB];
__device__ float    g_xa2[IN_DIMS*HID];
__device__ __align__(16) __half g_Ehf[NPAD*KS];
__device__ int g_deg[N_NODES];
__device__ int g_off[N_NODES + 1];
__device__ int g_pos[N_NODES];
__device__ int2 g_epack[MAXEDGE + N_NODES];

// ===== degree count (+ zero attr_part for this run) =====
__global__ void k_edge1(const int* __restrict__ ei, int E) {
    int i = blockIdx.x * blockDim.x + threadIdx.x;
    if (i < IN_DIMS*EMB) g_attr_part[i] = 0.f;
    if (i >= E + N_NODES) return;
    int d = (i < E) ? ei[E + i] : (i - E);
    atomicAdd(&g_deg[d], 1);
}

// ===== 3-barrier block scan; writes off+pos; self-cleans deg =====
__global__ __launch_bounds__(1024) void k_scan() {
    __shared__ int wsum[32];
    int t = threadIdx.x, lane = t & 31, wid = t >> 5;
    int base = t * 10;
    int v[10];
    int tot = 0;
    #pragma unroll
    for (int j = 0; j < 10; j++) {
        int idx = base + j;
        v[j] = (idx < N_NODES) ? g_deg[idx] : 0;
        tot += v[j];
    }
    int s = tot;
    #pragma unroll
    for (int o = 1; o < 32; o <<= 1) {
        int nv = __shfl_up_sync(0xffffffffu, s, o);
        if (lane >= o) s += nv;
    }
    if (lane == 31) wsum[wid] = s;
    __syncthreads();
    if (wid == 0) {
        int ws = wsum[lane];
        #pragma unroll
        for (int o = 1; o < 32; o <<= 1) {
            int nv = __shfl_up_sync(0xffffffffu, ws, o);
            if (lane >= o) ws += nv;
        }
        wsum[lane] = ws;
    }
    __syncthreads();
    int wex = wid ? wsum[wid - 1] : 0;
    int run = wex + s - tot;
    #pragma unroll
    for (int j = 0; j < 10; j++) {
        int idx = base + j;
        if (idx < N_NODES) {
            g_off[idx] = run;
            g_pos[idx] = run;
            g_deg[idx] = 0;
            run += v[j];
            if (idx == N_NODES - 1) g_off[N_NODES] = run;
        }
    }
}

// ===== attr1: 250 blocks x 40 rows, single-shot smem load, 1 sync =====
#define A1_ROWS 40
__global__ __launch_bounds__(256) void k_attr1(const float* __restrict__ x,
                                               const float* __restrict__ W1) {
    __shared__ float xs[A1_ROWS*IN_DIMS];   // 20 KB
    __shared__ float ws[A1_ROWS*EMB];       // 10 KB
    int t = threadIdx.x;
    int rbase = blockIdx.x * A1_ROWS;

    #pragma unroll
    for (int i = 0; i < 5; i++)
        ((float4*)xs)[t + i*256] =
            ((const float4*)x)[(size_t)rbase*32 + t + i*256];
    #pragma unroll
    for (int i = 0; i < 3; i++) {
        int v = t + i*256;
        if (v < A1_ROWS*EMB/4)
            ((float4*)ws)[v] = ((const float4*)W1)[(size_t)rbase*16 + v];
    }
    __syncthreads();

    int i0 = (t >> 4) * 8;
    int e0 = (t & 15) * 4;
    float acc[8][4];
    #pragma unroll
    for (int a = 0; a < 8; a++)
        #pragma unroll
        for (int b = 0; b < 4; b++) acc[a][b] = 0.f;

    #pragma unroll 4
    for (int rr = 0; rr < A1_ROWS; rr++) {
        float wv[4];
        #pragma unroll
        for (int j = 0; j < 4; j++) wv[j] = ws[rr*EMB + e0 + j];
        #pragma unroll
        for (int ii = 0; ii < 8; ii++) {
            float xv = xs[rr*IN_DIMS + i0 + ii];
            #pragma unroll
            for (int j = 0; j < 4; j++) acc[ii][j] += xv * wv[j];
        }
    }
    #pragma unroll
    for (int ii = 0; ii < 8; ii++)
        #pragma unroll
        for (int j = 0; j < 4; j++)
            atomicAdd(&g_attr_part[(i0+ii)*EMB + e0 + j], acc[ii][j]);
}

// ===== fused encoder, 256 thr / 32 nodes per block (R10 measured-best) =====
extern __shared__ float s_enc[];
__global__ __launch_bounds__(256) void k_enc(const float* __restrict__ x,
                                             const float* __restrict__ W1,
                                             const float* __restrict__ b1,
                                             const float* __restrict__ W2,
                                             const float* __restrict__ att_s,
                                             const float* __restrict__ att_d) {
    float* Ws1 = s_enc;            //  8192 floats
    float* Ws2 = s_enc + 8192;     //  4096
    float* xs  = s_enc + 12288;    //  4096 (32 x 128)
    float* hs  = s_enc + 16384;    //  2048 (32 x 64)
    __shared__ float As[HID], Ad[HID], Bs1[EMB];

    int t = threadIdx.x;
    int nbase = blockIdx.x * 32;

    #pragma unroll
    for (int i = 0; i < 8; i++)
        ((float4*)Ws1)[t + i*256] = ((const float4*)W1)[t + i*256];
    #pragma unroll
    for (int i = 0; i < 4; i++)
        ((float4*)Ws2)[t + i*256] = ((const float4*)W2)[t + i*256];
    #pragma unroll
    for (int i = 0; i < 4; i++) {
        int v = t + i*256;
        int n = nbase + (v >> 5);
        ((float4*)xs)[v] = (n < N_NODES)
            ? ((const float4*)x)[(size_t)nbase*32 + v] : make_float4(0,0,0,0);
    }
    if (t < HID) { As[t] = att_s[t]; Ad[t] = att_d[t]; }
    else if (t < 128) { Bs1[t - HID] = b1[t - HID]; }
    __syncthreads();

    int nl = t >> 4;
    int e0 = (t & 15) * 4;

    #pragma unroll
    for (int it = 0; it < 2; it++) {
        int row = nl + it*16;
        float a0=0.f, a1=0.f, a2=0.f, a3=0.f;
        const float* xr = &xs[row*IN_DIMS];
        #pragma unroll 4
        for (int k = 0; k < IN_DIMS; k++) {
            float xv = xr[k];
            float4 w = *(const float4*)&Ws1[k*EMB + e0];
            a0 += xv*w.x; a1 += xv*w.y; a2 += xv*w.z; a3 += xv*w.w;
        }
        *(float4*)&hs[row*EMB + e0] = make_float4(
            fmaxf(a0 + Bs1[e0+0], 0.f), fmaxf(a1 + Bs1[e0+1], 0.f),
            fmaxf(a2 + Bs1[e0+2], 0.f), fmaxf(a3 + Bs1[e0+3], 0.f));
    }
    __syncthreads();

    #pragma unroll
    for (int it = 0; it < 2; it++) {
        int row = nl + it*16;
        int n = nbase + row;
        float a0=0.f, a1=0.f, a2=0.f, a3=0.f;
        const float* hr = &hs[row*EMB];
        #pragma unroll 8
        for (int k = 0; k < EMB; k++) {
            float hv = hr[k];
            float4 w = *(const float4*)&Ws2[k*HID + e0];
            a0 += hv*w.x; a1 += hv*w.y; a2 += hv*w.z; a3 += hv*w.w;
        }
        if (n < N_NODES)
            *(float4*)&g_hp[(size_t)n*HID + e0] = make_float4(a0, a1, a2, a3);
        float ps = a0*As[e0] + a1*As[e0+1] + a2*As[e0+2] + a3*As[e0+3];
        float pd = a0*Ad[e0] + a1*Ad[e0+1] + a2*Ad[e0+2] + a3*Ad[e0+3];
        #pragma unroll
        for (int o = 8; o; o >>= 1) {
            ps += __shfl_down_sync(0xffffffffu, ps, o, 16);
            pd += __shfl_down_sync(0xffffffffu, pd, o, 16);
        }
        if ((t & 15) == 0 && n < N_NODES) { g_asrc[n] = ps; g_adst[n] = pd; }
    }
}

// ===== weight + scatter into CSR slots =====
__global__ void k_edge2(const int* __restrict__ ei, int E) {
    int i = blockIdx.x * blockDim.x + threadIdx.x;
    if (i >= E + N_NODES) return;
    int s, d;
    if (i < E) { s = ei[i]; d = ei[E + i]; } else { s = d = i - E; }
    float e = g_asrc[s] + g_adst[d];
    e = (e > 0.f) ? e : NEG_SLOPE * e;
    float w = __expf(e);
    int pos = atomicAdd(&g_pos[d], 1);
    g_epack[pos] = make_int2(s, __float_as_int(w));
}

// ===== warp per dst, 4x unrolled gathers, bias + fp16 split =====
__global__ void k_aggr(const float* __restrict__ bg) {
    int d = (blockIdx.x * blockDim.x + threadIdx.x) >> 5;
    int lane = threadIdx.x & 31;
    if (d >= N_NODES) return;
    int beg = g_off[d], end = g_off[d + 1];
    float wsum = 0.f, a0 = 0.f, a1 = 0.f;
    int p = beg;
    for (; p + 4 <= end; p += 4) {
        int2 e0 = g_epack[p];
        int2 e1 = g_epack[p+1];
        int2 e2 = g_epack[p+2];
        int2 e3 = g_epack[p+3];
        const float* r0 = &g_hp[(size_t)e0.x * HID];
        const float* r1 = &g_hp[(size_t)e1.x * HID];
        const float* r2 = &g_hp[(size_t)e2.x * HID];
        const float* r3 = &g_hp[(size_t)e3.x * HID];
        float h00 = r0[lane],    h01 = r0[32+lane];
        float h10 = r1[lane],    h11 = r1[32+lane];
        float h20 = r2[lane],    h21 = r2[32+lane];
        float h30 = r3[lane],    h31 = r3[32+lane];
        float w0 = __int_as_float(e0.y);
        float w1 = __int_as_float(e1.y);
        float w2 = __int_as_float(e2.y);
        float w3 = __int_as_float(e3.y);
        wsum += (w0 + w1) + (w2 + w3);
        a0 += h00*w0 + h10*w1 + h20*w2 + h30*w3;
        a1 += h01*w0 + h11*w1 + h21*w2 + h31*w3;
    }
    for (; p < end; p++) {
        int2 pk = g_epack[p];
        float w = __int_as_float(pk.y);
        const float* r = &g_hp[(size_t)pk.x * HID];
        wsum += w;
        a0 += r[lane] * w;
        a1 += r[32+lane] * w;
    }
    float inv = 1.f / wsum;
    float v0 = a0 * inv + bg[lane];
    float v1 = a1 * inv + bg[lane + 32];
    g_embP[(size_t)d*HID + lane]      = v0;
    g_embP[(size_t)d*HID + 32 + lane] = v1;
    __half h0 = __float2half(v0);
    __half l0 = __float2half(v0 - __half2float(h0));
    __half h1 = __float2half(v1);
    __half l1 = __float2half(v1 - __half2float(h1));
    size_t eb = (size_t)d * KS;
    g_Ehf[eb + lane]      = h0;
    g_Ehf[eb + 32 + lane] = h1;
    g_Ehf[eb + 64 + lane] = l0;
    g_Ehf[eb + 96 + lane] = l1;
}

__global__ __launch_bounds__(256) void k_attr2(const float* __restrict__ b1,
                                               const float* __restrict__ W2,
                                               const float* __restrict__ b2) {
    __shared__ float xa1[IN_DIMS*EMB];
    __shared__ float W2s[EMB*HID];
    int t = threadIdx.x;
    for (int i = t; i < IN_DIMS*EMB; i += 256)
        xa1[i] = fmaxf(g_attr_part[i] + b1[i % EMB], 0.f);
    for (int i = t; i < EMB*HID; i += 256) W2s[i] = W2[i];
    __syncthreads();
    int i0 = (t >> 4) * 8;
    int h0 = (t & 15) * 4;
    float acc[8][4];
    #pragma unroll
    for (int a = 0; a < 8; a++)
        #pragma unroll
        for (int b = 0; b < 4; b++) acc[a][b] = 0.f;
    for (int k = 0; k < EMB; k++) {
        float wv[4];
        #pragma unroll
        for (int j = 0; j < 4; j++) wv[j] = W2s[k*HID + h0 + j];
        #pragma unroll
        for (int ii = 0; ii < 8; ii++) {
            float xv = xa1[(i0+ii)*EMB + k];
            #pragma unroll
            for (int j = 0; j < 4; j++) acc[ii][j] += xv * wv[j];
        }
    }
    #pragma unroll
    for (int ii = 0; ii < 8; ii++)
        #pragma unroll
        for (int j = 0; j < 4; j++)
            g_xa2[(i0+ii)*HID + h0 + j] = acc[ii][j] + b2[h0 + j];
}

__global__ __launch_bounds__(256) void k_xout(float* __restrict__ out) {
    __shared__ float xa[IN_DIMS*(HID+1)];
    __shared__ float es[32*HID];
    int t = threadIdx.x;
    for (int i = t; i < IN_DIMS*HID; i += 256) {
        int r = i / HID, c = i % HID;
        xa[r*(HID+1) + c] = g_xa2[i];
    }
    int nb = blockIdx.x * 32;
    for (int i = t; i < 32*HID; i += 256) es[i] = g_embP[(size_t)nb*HID + i];
    __syncthreads();
    int nl = t >> 3;
    int ib = (t & 7) * 16;
    const float* e = &es[nl*HID];
    int n = nb + nl;
    if (n >= N_NODES) return;
    for (int ii = 0; ii < 16; ii++) {
        int i = ib + ii;
        const float* w = &xa[i*(HID+1)];
        float acc = 0.f;
        #pragma unroll 8
        for (int k = 0; k < HID; k++) acc += e[k]*w[k];
        out[(size_t)n*IN_DIMS + i] = acc;
    }
}

// ===== s_ GEMM: 512 thr, fully smem-staged float4 stores =====
#define ROWB 272
#define ROWB_B 144
#define BOFF 34816
#define SMEM_S 69632
#define TRS 132

__device__ __forceinline__ uint32_t smem_u32(const void* p) {
    uint32_t a;
    asm("{ .reg .u64 t; cvta.to.shared.u64 t, %1; cvt.u32.u64 %0, t; }" : "=r"(a) : "l"(p));
    return a;
}
__device__ __forceinline__ void ldsm4(uint32_t addr, uint32_t& r0, uint32_t& r1,
                                      uint32_t& r2, uint32_t& r3) {
    asm volatile("ldmatrix.sync.aligned.m8n8.x4.shared.b16 {%0,%1,%2,%3}, [%4];"
                 : "=r"(r0), "=r"(r1), "=r"(r2), "=r"(r3) : "r"(addr));
}
__device__ __forceinline__ void mma_f32(float c[4], uint32_t a0, uint32_t a1,
                                        uint32_t a2, uint32_t a3,
                                        uint32_t b0, uint32_t b1) {
    asm volatile(
        "mma.sync.aligned.m16n8k16.row.col.f32.f16.f16.f32 "
        "{%0,%1,%2,%3}, {%4,%5,%6,%7}, {%8,%9}, {%0,%1,%2,%3};"
        : "+f"(c[0]), "+f"(c[1]), "+f"(c[2]), "+f"(c[3])
        : "r"(a0), "r"(a1), "r"(a2), "r"(a3), "r"(b0), "r"(b1));
}

extern __shared__ char smem_s[];

__global__ __launch_bounds__(512, 2) void k_s_mma(float* __restrict__ sout) {
    int b = blockIdx.x;
    int ti = 0;
    {
        int rem = b, rowlen = NT;
        while (rem >= rowlen) { rem -= rowlen; ti++; rowlen--; }
        b = rem;
    }
    int tj = ti + b;

    int t = threadIdx.x;
    int warp = t >> 5, lane = t & 31;
    int wm = warp >> 1, wn = warp & 1;     // 8x2 warps: 16x64 warp tile
    int g = lane >> 2, tq = lane & 3;
    int q = lane >> 3, r8 = lane & 7;

    const __half* gA = &g_Ehf[(size_t)ti * TILE * KS];
    const __half* gB = &g_Ehf[(size_t)tj * TILE * KS];
    #pragma unroll
    for (int i = 0; i < 4; i++) {
        int v = i * 512 + t;
        int row = v >> 4;
        int c16 = v & 15;
        *(float4*)(smem_s + row*ROWB + c16*16) = *(const float4*)(gA + row*KS + c16*8);
    }
    #pragma unroll
    for (int i = 0; i < 2; i++) {
        int v = i * 512 + t;
        int row = v >> 3;
        int c8 = v & 7;
        *(float4*)(smem_s + BOFF + row*ROWB_B + c8*16) = *(const float4*)(gB + row*KS + c8*8);
    }
    __syncthreads();

    uint32_t sA = smem_u32(smem_s);
    uint32_t sB = sA + BOFF;

    uint32_t aAddr = sA + (uint32_t)(wm*16 + r8 + (q & 1)*8)*ROWB + (uint32_t)((q >> 1)*8)*2;
    uint32_t bAddr[4];
    #pragma unroll
    for (int n2 = 0; n2 < 4; n2++)
        bAddr[n2] = sB + (uint32_t)(wn*64 + n2*16 + r8 + (q >> 1)*8)*ROWB_B + (uint32_t)((q & 1)*8)*2;

    float c[8][4];
    #pragma unroll
    for (int nt = 0; nt < 8; nt++)
        #pragma unroll
        for (int rr = 0; rr < 4; rr++) c[nt][rr] = 0.f;

    #pragma unroll
    for (int kk = 0; kk < 4; kk++) {
        uint32_t ka = (uint32_t)kk * 32;
        uint32_t ah[4], al[4];
        ldsm4(aAddr + ka,       ah[0], ah[1], ah[2], ah[3]);
        ldsm4(aAddr + 128 + ka, al[0], al[1], al[2], al[3]);
        #pragma unroll
        for (int n2 = 0; n2 < 4; n2++) {
            uint32_t b0, b1, b2, b3;
            ldsm4(bAddr[n2] + ka, b0, b1, b2, b3);
            int nt = n2 * 2;
            mma_f32(c[nt],   ah[0], ah[1], ah[2], ah[3], b0, b1);
            mma_f32(c[nt+1], ah[0], ah[1], ah[2], ah[3], b2, b3);
            mma_f32(c[nt],   al[0], al[1], al[2], al[3], b0, b1);
            mma_f32(c[nt+1], al[0], al[1], al[2], al[3], b2, b3);
        }
    }

    #pragma unroll
    for (int nt = 0; nt < 8; nt++)
        #pragma unroll
        for (int rr = 0; rr < 4; rr++)
            c[nt][rr] = 1.f / (1.f + __expf(-c[nt][rr]));

    int rows_i = N_NODES - ti*TILE; if (rows_i > TILE) rows_i = TILE;
    int cols_j = N_NODES - tj*TILE; if (cols_j > TILE) cols_j = TILE;

    // --- stage normal tile row-major, write contiguous float4 rows ---
    __syncthreads();                      // tiles dead; reuse smem
    float* tr = (float*)smem_s;
    #pragma unroll
    for (int rr = 0; rr < 2; rr++) {
        int lr = wm*16 + g + rr*8;
        #pragma unroll
        for (int nt = 0; nt < 8; nt++) {
            int lc = wn*64 + nt*8 + tq*2;
            tr[lr*TRS + lc]     = c[nt][rr*2];
            tr[lr*TRS + lc + 1] = c[nt][rr*2 + 1];
        }
    }
    __syncthreads();
    #pragma unroll
    for (int i = 0; i < 8; i++) {
        int v = i*512 + t;
        int row = v >> 5;
        int c4 = (v & 31) * 4;
        if (row < rows_i && c4 < cols_j)
            *(float4*)&sout[(size_t)(ti*TILE + row)*N_NODES + tj*TILE + c4] =
                *(float4*)&tr[row*TRS + c4];
    }

    // --- mirror tile: stage transposed, write contiguous float4 rows ---
    if (ti != tj) {
        __syncthreads();
        #pragma unroll
        for (int rr = 0; rr < 2; rr++) {
            int lr = wm*16 + g + rr*8;
            #pragma unroll
            for (int nt = 0; nt < 8; nt++) {
                int lc = wn*64 + nt*8 + tq*2;
                tr[lc*TRS + lr]     = c[nt][rr*2];
                tr[(lc+1)*TRS + lr] = c[nt][rr*2 + 1];
            }
        }
        __syncthreads();
        #pragma unroll
        for (int i = 0; i < 8; i++) {
            int v = i*512 + t;
            int row = v >> 5;          // mirror row = original column
            int c4 = (v & 31) * 4;     // mirror col = original row
            if (row < cols_j && c4 < rows_i)
                *(float4*)&sout[(size_t)(tj*TILE + row)*N_NODES + ti*TILE + c4] =
                    *(float4*)&tr[row*TRS + c4];
        }
    }
}

// ---------------- launch ----------------
extern "C" void kernel_launch(void* const* d_in, const int* in_sizes, int n_in,
                              void* d_out, int out_size) {
    const float* x       = (const float*)d_in[0];
    const int*   ei      = (const int*)d_in[1];
    const float* W_stru  = (const float*)d_in[3];
    const float* b_stru  = (const float*)d_in[4];
    const float* W_gat   = (const float*)d_in[5];
    const float* att_src = (const float*)d_in[6];
    const float* att_dst = (const float*)d_in[7];
    const float* b_gat   = (const float*)d_in[8];
    const float* W_attr1 = (const float*)d_in[9];
    const float* b_attr1 = (const float*)d_in[10];
    const float* W_attr2 = (const float*)d_in[11];
    const float* b_attr2 = (const float*)d_in[12];

    int E = in_sizes[1] / 2;
    int EN = E + N_NODES;

    float* out   = (float*)d_out;
    float* x_out = out;
    float* s_out = out + (size_t)N_NODES * IN_DIMS;

    cudaFuncSetAttribute(k_enc, cudaFuncAttributeMaxDynamicSharedMemorySize, 73728);
    cudaFuncSetAttribute(k_s_mma, cudaFuncAttributeMaxDynamicSharedMemorySize, SMEM_S);

    k_edge1 <<<(EN + 255) / 256, 256>>>(ei, E);
    k_scan  <<<1, 1024>>>();
    k_attr1 <<<N_NODES / A1_ROWS, 256>>>(x, W_attr1);
    k_enc   <<<(N_NODES + 31) / 32, 256, 73728>>>(x, W_stru, b_stru, W_gat, att_src, att_dst);
    k_edge2 <<<(EN + 255) / 256, 256>>>(ei, E);
    k_aggr  <<<(N_NODES * 32 + 255) / 256, 256>>>(b_gat);
    k_attr2 <<<1, 256>>>(b_attr1, W_attr2, b_attr2);
    k_xout  <<<(N_NODES + 31) / 32, 256>>>(x_out);
    k_s_mma <<<NT * (NT + 1) / 2, 512, SMEM_S>>>(s_out);
}

// round 14
// speedup vs baseline: 1.2089x; 1.0195x over previous
#include <cuda_runtime.h>
#include <cuda_fp16.h>
#include <math.h>
#include <stdint.h>

#define N_NODES 10000
#define IN_DIMS 128
#define EMB 64
#define HID 64
#define NEG_SLOPE 0.2f
#define TILE 128
#define NT 79
#define NPAD (NT*TILE)
#define MAXEDGE 400000
#define KS 128                // [hi(64) | lo(64)] fp16 split rows

// ---------------- scratch ----------------
__device__ float    g_hp[N_NODES*HID];
__device__ float    g_asrc[N_NODES];
__device__ float    g_adst[N_NODES];
__device__ float    g_embP[N_NODES*HID];
__device__ float    g_attr_part[IN_DIMS*EMB];
__device__ float    g_xa2[IN_DIMS*HID];
__device__ __align__(16) __half g_Ehf[NPAD*KS];
__device__ int g_deg[N_NODES];
__device__ int g_off[N_NODES + 1];
__device__ int g_pos[N_NODES];
__device__ int2 g_epack[MAXEDGE + N_NODES];

// ===== degree count (+ zero attr_part) =====
__global__ void k_edge1(const int* __restrict__ ei, int E) {
    int i = blockIdx.x * blockDim.x + threadIdx.x;
    if (i < IN_DIMS*EMB) g_attr_part[i] = 0.f;
    if (i >= E + N_NODES) return;
    int d = (i < E) ? ei[E + i] : (i - E);
    atomicAdd(&g_deg[d], 1);
}

// ===== 3-barrier block scan =====
__global__ __launch_bounds__(1024) void k_scan() {
    __shared__ int wsum[32];
    int t = threadIdx.x, lane = t & 31, wid = t >> 5;
    int base = t * 10;
    int v[10];
    int tot = 0;
    #pragma unroll
    for (int j = 0; j < 10; j++) {
        int idx = base + j;
        v[j] = (idx < N_NODES) ? g_deg[idx] : 0;
        tot += v[j];
    }
    int s = tot;
    #pragma unroll
    for (int o = 1; o < 32; o <<= 1) {
        int nv = __shfl_up_sync(0xffffffffu, s, o);
        if (lane >= o) s += nv;
    }
    if (lane == 31) wsum[wid] = s;
    __syncthreads();
    if (wid == 0) {
        int ws = wsum[lane];
        #pragma unroll
        for (int o = 1; o < 32; o <<= 1) {
            int nv = __shfl_up_sync(0xffffffffu, ws, o);
            if (lane >= o) ws += nv;
        }
        wsum[lane] = ws;
    }
    __syncthreads();
    int wex = wid ? wsum[wid - 1] : 0;
    int run = wex + s - tot;
    #pragma unroll
    for (int j = 0; j < 10; j++) {
        int idx = base + j;
        if (idx < N_NODES) {
            g_off[idx] = run;
            g_pos[idx] = run;
            g_deg[idx] = 0;
            run += v[j];
            if (idx == N_NODES - 1) g_off[N_NODES] = run;
        }
    }
}

// ===== attr1: 250 blocks x 40 rows =====
#define A1_ROWS 40
__global__ __launch_bounds__(256) void k_attr1(const float* __restrict__ x,
                                               const float* __restrict__ W1) {
    __shared__ float xs[A1_ROWS*IN_DIMS];
    __shared__ float ws[A1_ROWS*EMB];
    int t = threadIdx.x;
    int rbase = blockIdx.x * A1_ROWS;
    #pragma unroll
    for (int i = 0; i < 5; i++)
        ((float4*)xs)[t + i*256] =
            ((const float4*)x)[(size_t)rbase*32 + t + i*256];
    #pragma unroll
    for (int i = 0; i < 3; i++) {
        int v = t + i*256;
        if (v < A1_ROWS*EMB/4)
            ((float4*)ws)[v] = ((const float4*)W1)[(size_t)rbase*16 + v];
    }
    __syncthreads();
    int i0 = (t >> 4) * 8;
    int e0 = (t & 15) * 4;
    float acc[8][4];
    #pragma unroll
    for (int a = 0; a < 8; a++)
        #pragma unroll
        for (int b = 0; b < 4; b++) acc[a][b] = 0.f;
    #pragma unroll 4
    for (int rr = 0; rr < A1_ROWS; rr++) {
        float wv[4];
        #pragma unroll
        for (int j = 0; j < 4; j++) wv[j] = ws[rr*EMB + e0 + j];
        #pragma unroll
        for (int ii = 0; ii < 8; ii++) {
            float xv = xs[rr*IN_DIMS + i0 + ii];
            #pragma unroll
            for (int j = 0; j < 4; j++) acc[ii][j] += xv * wv[j];
        }
    }
    #pragma unroll
    for (int ii = 0; ii < 8; ii++)
        #pragma unroll
        for (int j = 0; j < 4; j++)
            atomicAdd(&g_attr_part[(i0+ii)*EMB + e0 + j], acc[ii][j]);
}

// ===== fused encoder, 256 thr / 32 nodes (measured best) =====
extern __shared__ float s_enc[];
__global__ __launch_bounds__(256) void k_enc(const float* __restrict__ x,
                                             const float* __restrict__ W1,
                                             const float* __restrict__ b1,
                                             const float* __restrict__ W2,
                                             const float* __restrict__ att_s,
                                             const float* __restrict__ att_d) {
    float* Ws1 = s_enc;
    float* Ws2 = s_enc + 8192;
    float* xs  = s_enc + 12288;
    float* hs  = s_enc + 16384;
    __shared__ float As[HID], Ad[HID], Bs1[EMB];

    int t = threadIdx.x;
    int nbase = blockIdx.x * 32;

    #pragma unroll
    for (int i = 0; i < 8; i++)
        ((float4*)Ws1)[t + i*256] = ((const float4*)W1)[t + i*256];
    #pragma unroll
    for (int i = 0; i < 4; i++)
        ((float4*)Ws2)[t + i*256] = ((const float4*)W2)[t + i*256];
    #pragma unroll
    for (int i = 0; i < 4; i++) {
        int v = t + i*256;
        int n = nbase + (v >> 5);
        ((float4*)xs)[v] = (n < N_NODES)
            ? ((const float4*)x)[(size_t)nbase*32 + v] : make_float4(0,0,0,0);
    }
    if (t < HID) { As[t] = att_s[t]; Ad[t] = att_d[t]; }
    else if (t < 128) { Bs1[t - HID] = b1[t - HID]; }
    __syncthreads();

    int nl = t >> 4;
    int e0 = (t & 15) * 4;

    #pragma unroll
    for (int it = 0; it < 2; it++) {
        int row = nl + it*16;
        float a0=0.f, a1=0.f, a2=0.f, a3=0.f;
        const float* xr = &xs[row*IN_DIMS];
        #pragma unroll 4
        for (int k = 0; k < IN_DIMS; k++) {
            float xv = xr[k];
            float4 w = *(const float4*)&Ws1[k*EMB + e0];
            a0 += xv*w.x; a1 += xv*w.y; a2 += xv*w.z; a3 += xv*w.w;
        }
        *(float4*)&hs[row*EMB + e0] = make_float4(
            fmaxf(a0 + Bs1[e0+0], 0.f), fmaxf(a1 + Bs1[e0+1], 0.f),
            fmaxf(a2 + Bs1[e0+2], 0.f), fmaxf(a3 + Bs1[e0+3], 0.f));
    }
    __syncthreads();

    #pragma unroll
    for (int it = 0; it < 2; it++) {
        int row = nl + it*16;
        int n = nbase + row;
        float a0=0.f, a1=0.f, a2=0.f, a3=0.f;
        const float* hr = &hs[row*EMB];
        #pragma unroll 8
        for (int k = 0; k < EMB; k++) {
            float hv = hr[k];
            float4 w = *(const float4*)&Ws2[k*HID + e0];
            a0 += hv*w.x; a1 += hv*w.y; a2 += hv*w.z; a3 += hv*w.w;
        }
        if (n < N_NODES)
            *(float4*)&g_hp[(size_t)n*HID + e0] = make_float4(a0, a1, a2, a3);
        float ps = a0*As[e0] + a1*As[e0+1] + a2*As[e0+2] + a3*As[e0+3];
        float pd = a0*Ad[e0] + a1*Ad[e0+1] + a2*Ad[e0+2] + a3*Ad[e0+3];
        #pragma unroll
        for (int o = 8; o; o >>= 1) {
            ps += __shfl_down_sync(0xffffffffu, ps, o, 16);
            pd += __shfl_down_sync(0xffffffffu, pd, o, 16);
        }
        if ((t & 15) == 0 && n < N_NODES) { g_asrc[n] = ps; g_adst[n] = pd; }
    }
}

// ===== weight + scatter =====
__global__ void k_edge2(const int* __restrict__ ei, int E) {
    int i = blockIdx.x * blockDim.x + threadIdx.x;
    if (i >= E + N_NODES) return;
    int s, d;
    if (i < E) { s = ei[i]; d = ei[E + i]; } else { s = d = i - E; }
    float e = g_asrc[s] + g_adst[d];
    e = (e > 0.f) ? e : NEG_SLOPE * e;
    float w = __expf(e);
    int pos = atomicAdd(&g_pos[d], 1);
    g_epack[pos] = make_int2(s, __float_as_int(w));
}

// ===== warp per dst: float2 gathers (features 2*lane, 2*lane+1) =====
__global__ void k_aggr(const float* __restrict__ bg) {
    int d = (blockIdx.x * blockDim.x + threadIdx.x) >> 5;
    int lane = threadIdx.x & 31;
    if (d >= N_NODES) return;
    int beg = g_off[d], end = g_off[d + 1];
    float wsum = 0.f, a0 = 0.f, a1 = 0.f;
    int f = lane * 2;
    int p = beg;
    for (; p + 4 <= end; p += 4) {
        int2 e0 = g_epack[p];
        int2 e1 = g_epack[p+1];
        int2 e2 = g_epack[p+2];
        int2 e3 = g_epack[p+3];
        float2 h0 = *(const float2*)&g_hp[(size_t)e0.x * HID + f];
        float2 h1 = *(const float2*)&g_hp[(size_t)e1.x * HID + f];
        float2 h2 = *(const float2*)&g_hp[(size_t)e2.x * HID + f];
        float2 h3 = *(const float2*)&g_hp[(size_t)e3.x * HID + f];
        float w0 = __int_as_float(e0.y);
        float w1 = __int_as_float(e1.y);
        float w2 = __int_as_float(e2.y);
        float w3 = __int_as_float(e3.y);
        wsum += (w0 + w1) + (w2 + w3);
        a0 += h0.x*w0 + h1.x*w1 + h2.x*w2 + h3.x*w3;
        a1 += h0.y*w0 + h1.y*w1 + h2.y*w2 + h3.y*w3;
    }
    for (; p < end; p++) {
        int2 pk = g_epack[p];
        float w = __int_as_float(pk.y);
        float2 h = *(const float2*)&g_hp[(size_t)pk.x * HID + f];
        wsum += w;
        a0 += h.x * w;
        a1 += h.y * w;
    }
    float inv = 1.f / wsum;
    float v0 = a0 * inv + bg[f];
    float v1 = a1 * inv + bg[f + 1];
    *(float2*)&g_embP[(size_t)d*HID + f] = make_float2(v0, v1);
    __half h0 = __float2half(v0);
    __half l0 = __float2half(v0 - __half2float(h0));
    __half h1 = __float2half(v1);
    __half l1 = __float2half(v1 - __half2float(h1));
    size_t eb = (size_t)d * KS;
    __half2* Eh = (__half2*)&g_Ehf[eb + f];
    __half2* El = (__half2*)&g_Ehf[eb + 64 + f];
    *Eh = __halves2half2(h0, h1);
    *El = __halves2half2(l0, l1);
}

__global__ __launch_bounds__(256) void k_attr2(const float* __restrict__ b1,
                                               const float* __restrict__ W2,
                                               const float* __restrict__ b2) {
    __shared__ float xa1[IN_DIMS*EMB];
    __shared__ float W2s[EMB*HID];
    int t = threadIdx.x;
    for (int i = t; i < IN_DIMS*EMB; i += 256)
        xa1[i] = fmaxf(g_attr_part[i] + b1[i % EMB], 0.f);
    for (int i = t; i < EMB*HID; i += 256) W2s[i] = W2[i];
    __syncthreads();
    int i0 = (t >> 4) * 8;
    int h0 = (t & 15) * 4;
    float acc[8][4];
    #pragma unroll
    for (int a = 0; a < 8; a++)
        #pragma unroll
        for (int b = 0; b < 4; b++) acc[a][b] = 0.f;
    for (int k = 0; k < EMB; k++) {
        float wv[4];
        #pragma unroll
        for (int j = 0; j < 4; j++) wv[j] = W2s[k*HID + h0 + j];
        #pragma unroll
        for (int ii = 0; ii < 8; ii++) {
            float xv = xa1[(i0+ii)*EMB + k];
            #pragma unroll
            for (int j = 0; j < 4; j++) acc[ii][j] += xv * wv[j];
        }
    }
    #pragma unroll
    for (int ii = 0; ii < 8; ii++)
        #pragma unroll
        for (int j = 0; j < 4; j++)
            g_xa2[(i0+ii)*HID + h0 + j] = acc[ii][j] + b2[h0 + j];
}

__global__ __launch_bounds__(256) void k_xout(float* __restrict__ out) {
    __shared__ float xa[IN_DIMS*(HID+1)];
    __shared__ float es[32*HID];
    int t = threadIdx.x;
    for (int i = t; i < IN_DIMS*HID; i += 256) {
        int r = i / HID, c = i % HID;
        xa[r*(HID+1) + c] = g_xa2[i];
    }
    int nb = blockIdx.x * 32;
    for (int i = t; i < 32*HID; i += 256) es[i] = g_embP[(size_t)nb*HID + i];
    __syncthreads();
    int nl = t >> 3;
    int ib = (t & 7) * 16;
    const float* e = &es[nl*HID];
    int n = nb + nl;
    if (n >= N_NODES) return;
    for (int ii = 0; ii < 16; ii++) {
        int i = ib + ii;
        const float* w = &xa[i*(HID+1)];
        float acc = 0.f;
        #pragma unroll 8
        for (int k = 0; k < HID; k++) acc += e[k]*w[k];
        out[(size_t)n*IN_DIMS + i] = acc;
    }
}

// ===== s_ GEMM: 512 thr, direct float2 normal store + staged mirror =====
#define ROWB 272
#define ROWB_B 144
#define BOFF 34816
#define SMEM_S 69632
#define TRS 132

__device__ __forceinline__ uint32_t smem_u32(const void* p) {
    uint32_t a;
    asm("{ .reg .u64 t; cvta.to.shared.u64 t, %1; cvt.u32.u64 %0, t; }" : "=r"(a) : "l"(p));
    return a;
}
__device__ __forceinline__ void ldsm4(uint32_t addr, uint32_t& r0, uint32_t& r1,
                                      uint32_t& r2, uint32_t& r3) {
    asm volatile("ldmatrix.sync.aligned.m8n8.x4.shared.b16 {%0,%1,%2,%3}, [%4];"
                 : "=r"(r0), "=r"(r1), "=r"(r2), "=r"(r3) : "r"(addr));
}
__device__ __forceinline__ void mma_f32(float c[4], uint32_t a0, uint32_t a1,
                                        uint32_t a2, uint32_t a3,
                                        uint32_t b0, uint32_t b1) {
    asm volatile(
        "mma.sync.aligned.m16n8k16.row.col.f32.f16.f16.f32 "
        "{%0,%1,%2,%3}, {%4,%5,%6,%7}, {%8,%9}, {%0,%1,%2,%3};"
        : "+f"(c[0]), "+f"(c[1]), "+f"(c[2]), "+f"(c[3])
        : "r"(a0), "r"(a1), "r"(a2), "r"(a3), "r"(b0), "r"(b1));
}

extern __shared__ char smem_s[];

__global__ __launch_bounds__(512, 2) void k_s_mma(float* __restrict__ sout) {
    int b = blockIdx.x;
    int ti = 0;
    {
        int rem = b, rowlen = NT;
        while (rem >= rowlen) { rem -= rowlen; ti++; rowlen--; }
        b = rem;
    }
    int tj = ti + b;

    int t = threadIdx.x;
    int warp = t >> 5, lane = t & 31;
    int wm = warp >> 1, wn = warp & 1;
    int g = lane >> 2, tq = lane & 3;
    int q = lane >> 3, r8 = lane & 7;

    const __half* gA = &g_Ehf[(size_t)ti * TILE * KS];
    const __half* gB = &g_Ehf[(size_t)tj * TILE * KS];
    #pragma unroll
    for (int i = 0; i < 4; i++) {
        int v = i * 512 + t;
        int row = v >> 4;
        int c16 = v & 15;
        *(float4*)(smem_s + row*ROWB + c16*16) = *(const float4*)(gA + row*KS + c16*8);
    }
    #pragma unroll
    for (int i = 0; i < 2; i++) {
        int v = i * 512 + t;
        int row = v >> 3;
        int c8 = v & 7;
        *(float4*)(smem_s + BOFF + row*ROWB_B + c8*16) = *(const float4*)(gB + row*KS + c8*8);
    }
    __syncthreads();

    uint32_t sA = smem_u32(smem_s);
    uint32_t sB = sA + BOFF;

    uint32_t aAddr = sA + (uint32_t)(wm*16 + r8 + (q & 1)*8)*ROWB + (uint32_t)((q >> 1)*8)*2;
    uint32_t bAddr[4];
    #pragma unroll
    for (int n2 = 0; n2 < 4; n2++)
        bAddr[n2] = sB + (uint32_t)(wn*64 + n2*16 + r8 + (q >> 1)*8)*ROWB_B + (uint32_t)((q & 1)*8)*2;

    float c[8][4];
    #pragma unroll
    for (int nt = 0; nt < 8; nt++)
        #pragma unroll
        for (int rr = 0; rr < 4; rr++) c[nt][rr] = 0.f;

    #pragma unroll
    for (int kk = 0; kk < 4; kk++) {
        uint32_t ka = (uint32_t)kk * 32;
        uint32_t ah[4], al[4];
        ldsm4(aAddr + ka,       ah[0], ah[1], ah[2], ah[3]);
        ldsm4(aAddr + 128 + ka, al[0], al[1], al[2], al[3]);
        #pragma unroll
        for (int n2 = 0; n2 < 4; n2++) {
            uint32_t b0, b1, b2, b3;
            ldsm4(bAddr[n2] + ka, b0, b1, b2, b3);
            int nt = n2 * 2;
            mma_f32(c[nt],   ah[0], ah[1], ah[2], ah[3], b0, b1);
            mma_f32(c[nt+1], ah[0], ah[1], ah[2], ah[3], b2, b3);
            mma_f32(c[nt],   al[0], al[1], al[2], al[3], b0, b1);
            mma_f32(c[nt+1], al[0], al[1], al[2], al[3], b2, b3);
        }
    }

    #pragma unroll
    for (int nt = 0; nt < 8; nt++)
        #pragma unroll
        for (int rr = 0; rr < 4; rr++)
            c[nt][rr] = 1.f / (1.f + __expf(-c[nt][rr]));

    // normal tile: direct row-major float2 stores
    #pragma unroll
    for (int rr = 0; rr < 2; rr++) {
        int gr = ti*TILE + wm*16 + g + rr*8;
        if (gr >= N_NODES) continue;
        size_t obase = (size_t)gr * N_NODES;
        #pragma unroll
        for (int nt = 0; nt < 8; nt++) {
            int gc = tj*TILE + wn*64 + nt*8 + tq*2;
            if (gc < N_NODES)
                *(float2*)&sout[obase + gc] =
                    make_float2(c[nt][rr*2], c[nt][rr*2 + 1]);
        }
    }

    // mirror tile via smem transpose stage
    if (ti != tj) {
        __syncthreads();
        float* tr = (float*)smem_s;
        #pragma unroll
        for (int rr = 0; rr < 2; rr++) {
            int lr = wm*16 + g + rr*8;
            #pragma unroll
            for (int nt = 0; nt < 8; nt++) {
                int lc = wn*64 + nt*8 + tq*2;
                tr[lc*TRS + lr]     = c[nt][rr*2];
                tr[(lc+1)*TRS + lr] = c[nt][rr*2 + 1];
            }
        }
        __syncthreads();
        int len = N_NODES - ti*TILE;
        if (len > TILE) len = TILE;
        int lr0 = lane * 4;
        #pragma unroll
        for (int rr2 = 0; rr2 < 8; rr2++) {
            int lc = warp*8 + rr2;
            int gcRow = tj*TILE + lc;
            if (gcRow < N_NODES && lr0 < len) {
                *(float4*)&sout[(size_t)gcRow*N_NODES + ti*TILE + lr0] =
                    *(float4*)&tr[lc*TRS + lr0];
            }
        }
    }
}

// ---------------- launch ----------------
extern "C" void kernel_launch(void* const* d_in, const int* in_sizes, int n_in,
                              void* d_out, int out_size) {
    const float* x       = (const float*)d_in[0];
    const int*   ei      = (const int*)d_in[1];
    const float* W_stru  = (const float*)d_in[3];
    const float* b_stru  = (const float*)d_in[4];
    const float* W_gat   = (const float*)d_in[5];
    const float* att_src = (const float*)d_in[6];
    const float* att_dst = (const float*)d_in[7];
    const float* b_gat   = (const float*)d_in[8];
    const float* W_attr1 = (const float*)d_in[9];
    const float* b_attr1 = (const float*)d_in[10];
    const float* W_attr2 = (const float*)d_in[11];
    const float* b_attr2 = (const float*)d_in[12];

    int E = in_sizes[1] / 2;
    int EN = E + N_NODES;

    float* out   = (float*)d_out;
    float* x_out = out;
    float* s_out = out + (size_t)N_NODES * IN_DIMS;

    cudaFuncSetAttribute(k_enc, cudaFuncAttributeMaxDynamicSharedMemorySize, 73728);
    cudaFuncSetAttribute(k_s_mma, cudaFuncAttributeMaxDynamicSharedMemorySize, SMEM_S);

    // order: launch #4 (ncu capture slot) = k_attr1 (verify rewrite)
    k_edge1 <<<(EN + 255) / 256, 256>>>(ei, E);
    k_scan  <<<1, 1024>>>();
    k_enc   <<<(N_NODES + 31) / 32, 256, 73728>>>(x, W_stru, b_stru, W_gat, att_src, att_dst);
    k_attr1 <<<N_NODES / A1_ROWS, 256>>>(x, W_attr1);
    k_edge2 <<<(EN + 255) / 256, 256>>>(ei, E);
    k_aggr  <<<(N_NODES * 32 + 255) / 256, 256>>>(b_gat);
    k_attr2 <<<1, 256>>>(b_attr1, W_attr2, b_attr2);
    k_xout  <<<(N_NODES + 31) / 32, 256>>>(x_out);
    k_s_mma <<<NT * (NT + 1) / 2, 512, SMEM_S>>>(s_out);
}

// round 15
// speedup vs baseline: 1.3033x; 1.0781x over previous
#include <cuda_runtime.h>
#include <cuda_fp16.h>
#include <math.h>
#include <stdint.h>

#define N_NODES 10000
#define IN_DIMS 128
#define EMB 64
#define HID 64
#define NEG_SLOPE 0.2f
#define TILE 128
#define NT 79
#define NPAD (NT*TILE)
#define MAXEDGE 400000
#define KS 128                // [hi(64) | lo(64)] fp16 split rows

// ---------------- scratch ----------------
__device__ float    g_hp[N_NODES*HID];
__device__ float    g_asrc[N_NODES];
__device__ float    g_adst[N_NODES];
__device__ float    g_embP[N_NODES*HID];
__device__ float    g_attr_part[IN_DIMS*EMB];
__device__ float    g_xa2[IN_DIMS*HID];
__device__ __align__(16) __half g_Ehf[NPAD*KS];
__device__ int g_deg[N_NODES];
__device__ int g_off[N_NODES + 1];
__device__ int g_pos[N_NODES];
__device__ int2 g_epack[MAXEDGE + N_NODES];

// fast sigmoid: 0.5*tanh(x/2)+0.5 (hardware tanh.approx, 1 MUFU op)
__device__ __forceinline__ float fsigmoid(float x) {
    float th;
    asm("tanh.approx.f32 %0, %1;" : "=f"(th) : "f"(x * 0.5f));
    return fmaf(th, 0.5f, 0.5f);
}

// ===== degree count (+ zero attr_part) =====
__global__ void k_edge1(const int* __restrict__ ei, int E) {
    int i = blockIdx.x * blockDim.x + threadIdx.x;
    if (i < IN_DIMS*EMB) g_attr_part[i] = 0.f;
    if (i >= E + N_NODES) return;
    int d = (i < E) ? ei[E + i] : (i - E);
    atomicAdd(&g_deg[d], 1);
}

// ===== 3-barrier block scan =====
__global__ __launch_bounds__(1024) void k_scan() {
    __shared__ int wsum[32];
    int t = threadIdx.x, lane = t & 31, wid = t >> 5;
    int base = t * 10;
    int v[10];
    int tot = 0;
    #pragma unroll
    for (int j = 0; j < 10; j++) {
        int idx = base + j;
        v[j] = (idx < N_NODES) ? g_deg[idx] : 0;
        tot += v[j];
    }
    int s = tot;
    #pragma unroll
    for (int o = 1; o < 32; o <<= 1) {
        int nv = __shfl_up_sync(0xffffffffu, s, o);
        if (lane >= o) s += nv;
    }
    if (lane == 31) wsum[wid] = s;
    __syncthreads();
    if (wid == 0) {
        int ws = wsum[lane];
        #pragma unroll
        for (int o = 1; o < 32; o <<= 1) {
            int nv = __shfl_up_sync(0xffffffffu, ws, o);
            if (lane >= o) ws += nv;
        }
        wsum[lane] = ws;
    }
    __syncthreads();
    int wex = wid ? wsum[wid - 1] : 0;
    int run = wex + s - tot;
    #pragma unroll
    for (int j = 0; j < 10; j++) {
        int idx = base + j;
        if (idx < N_NODES) {
            g_off[idx] = run;
            g_pos[idx] = run;
            g_deg[idx] = 0;
            run += v[j];
            if (idx == N_NODES - 1) g_off[N_NODES] = run;
        }
    }
}

// ===== attr1: 250 blocks x 40 rows =====
#define A1_ROWS 40
__global__ __launch_bounds__(256) void k_attr1(const float* __restrict__ x,
                                               const float* __restrict__ W1) {
    __shared__ float xs[A1_ROWS*IN_DIMS];
    __shared__ float ws[A1_ROWS*EMB];
    int t = threadIdx.x;
    int rbase = blockIdx.x * A1_ROWS;
    #pragma unroll
    for (int i = 0; i < 5; i++)
        ((float4*)xs)[t + i*256] =
            ((const float4*)x)[(size_t)rbase*32 + t + i*256];
    #pragma unroll
    for (int i = 0; i < 3; i++) {
        int v = t + i*256;
        if (v < A1_ROWS*EMB/4)
            ((float4*)ws)[v] = ((const float4*)W1)[(size_t)rbase*16 + v];
    }
    __syncthreads();
    int i0 = (t >> 4) * 8;
    int e0 = (t & 15) * 4;
    float acc[8][4];
    #pragma unroll
    for (int a = 0; a < 8; a++)
        #pragma unroll
        for (int b = 0; b < 4; b++) acc[a][b] = 0.f;
    #pragma unroll 4
    for (int rr = 0; rr < A1_ROWS; rr++) {
        float wv[4];
        #pragma unroll
        for (int j = 0; j < 4; j++) wv[j] = ws[rr*EMB + e0 + j];
        #pragma unroll
        for (int ii = 0; ii < 8; ii++) {
            float xv = xs[rr*IN_DIMS + i0 + ii];
            #pragma unroll
            for (int j = 0; j < 4; j++) acc[ii][j] += xv * wv[j];
        }
    }
    #pragma unroll
    for (int ii = 0; ii < 8; ii++)
        #pragma unroll
        for (int j = 0; j < 4; j++)
            atomicAdd(&g_attr_part[(i0+ii)*EMB + e0 + j], acc[ii][j]);
}

// ===== fused encoder, 256 thr / 32 nodes =====
extern __shared__ float s_enc[];
__global__ __launch_bounds__(256) void k_enc(const float* __restrict__ x,
                                             const float* __restrict__ W1,
                                             const float* __restrict__ b1,
                                             const float* __restrict__ W2,
                                             const float* __restrict__ att_s,
                                             const float* __restrict__ att_d) {
    float* Ws1 = s_enc;
    float* Ws2 = s_enc + 8192;
    float* xs  = s_enc + 12288;
    float* hs  = s_enc + 16384;
    __shared__ float As[HID], Ad[HID], Bs1[EMB];

    int t = threadIdx.x;
    int nbase = blockIdx.x * 32;

    #pragma unroll
    for (int i = 0; i < 8; i++)
        ((float4*)Ws1)[t + i*256] = ((const float4*)W1)[t + i*256];
    #pragma unroll
    for (int i = 0; i < 4; i++)
        ((float4*)Ws2)[t + i*256] = ((const float4*)W2)[t + i*256];
    #pragma unroll
    for (int i = 0; i < 4; i++) {
        int v = t + i*256;
        int n = nbase + (v >> 5);
        ((float4*)xs)[v] = (n < N_NODES)
            ? ((const float4*)x)[(size_t)nbase*32 + v] : make_float4(0,0,0,0);
    }
    if (t < HID) { As[t] = att_s[t]; Ad[t] = att_d[t]; }
    else if (t < 128) { Bs1[t - HID] = b1[t - HID]; }
    __syncthreads();

    int nl = t >> 4;
    int e0 = (t & 15) * 4;

    #pragma unroll
    for (int it = 0; it < 2; it++) {
        int row = nl + it*16;
        float a0=0.f, a1=0.f, a2=0.f, a3=0.f;
        const float* xr = &xs[row*IN_DIMS];
        #pragma unroll 4
        for (int k = 0; k < IN_DIMS; k++) {
            float xv = xr[k];
            float4 w = *(const float4*)&Ws1[k*EMB + e0];
            a0 += xv*w.x; a1 += xv*w.y; a2 += xv*w.z; a3 += xv*w.w;
        }
        *(float4*)&hs[row*EMB + e0] = make_float4(
            fmaxf(a0 + Bs1[e0+0], 0.f), fmaxf(a1 + Bs1[e0+1], 0.f),
            fmaxf(a2 + Bs1[e0+2], 0.f), fmaxf(a3 + Bs1[e0+3], 0.f));
    }
    __syncthreads();

    #pragma unroll
    for (int it = 0; it < 2; it++) {
        int row = nl + it*16;
        int n = nbase + row;
        float a0=0.f, a1=0.f, a2=0.f, a3=0.f;
        const float* hr = &hs[row*EMB];
        #pragma unroll 8
        for (int k = 0; k < EMB; k++) {
            float hv = hr[k];
            float4 w = *(const float4*)&Ws2[k*HID + e0];
            a0 += hv*w.x; a1 += hv*w.y; a2 += hv*w.z; a3 += hv*w.w;
        }
        if (n < N_NODES)
            *(float4*)&g_hp[(size_t)n*HID + e0] = make_float4(a0, a1, a2, a3);
        float ps = a0*As[e0] + a1*As[e0+1] + a2*As[e0+2] + a3*As[e0+3];
        float pd = a0*Ad[e0] + a1*Ad[e0+1] + a2*Ad[e0+2] + a3*Ad[e0+3];
        #pragma unroll
        for (int o = 8; o; o >>= 1) {
            ps += __shfl_down_sync(0xffffffffu, ps, o, 16);
            pd += __shfl_down_sync(0xffffffffu, pd, o, 16);
        }
        if ((t & 15) == 0 && n < N_NODES) { g_asrc[n] = ps; g_adst[n] = pd; }
    }
}

// ===== weight + scatter =====
__global__ void k_edge2(const int* __restrict__ ei, int E) {
    int i = blockIdx.x * blockDim.x + threadIdx.x;
    if (i >= E + N_NODES) return;
    int s, d;
    if (i < E) { s = ei[i]; d = ei[E + i]; } else { s = d = i - E; }
    float e = g_asrc[s] + g_adst[d];
    e = (e > 0.f) ? e : NEG_SLOPE * e;
    float w = __expf(e);
    int pos = atomicAdd(&g_pos[d], 1);
    g_epack[pos] = make_int2(s, __float_as_int(w));
}

// ===== warp per dst: float2 gathers =====
__global__ void k_aggr(const float* __restrict__ bg) {
    int d = (blockIdx.x * blockDim.x + threadIdx.x) >> 5;
    int lane = threadIdx.x & 31;
    if (d >= N_NODES) return;
    int beg = g_off[d], end = g_off[d + 1];
    float wsum = 0.f, a0 = 0.f, a1 = 0.f;
    int f = lane * 2;
    int p = beg;
    for (; p + 4 <= end; p += 4) {
        int2 e0 = g_epack[p];
        int2 e1 = g_epack[p+1];
        int2 e2 = g_epack[p+2];
        int2 e3 = g_epack[p+3];
        float2 h0 = *(const float2*)&g_hp[(size_t)e0.x * HID + f];
        float2 h1 = *(const float2*)&g_hp[(size_t)e1.x * HID + f];
        float2 h2 = *(const float2*)&g_hp[(size_t)e2.x * HID + f];
        float2 h3 = *(const float2*)&g_hp[(size_t)e3.x * HID + f];
        float w0 = __int_as_float(e0.y);
        float w1 = __int_as_float(e1.y);
        float w2 = __int_as_float(e2.y);
        float w3 = __int_as_float(e3.y);
        wsum += (w0 + w1) + (w2 + w3);
        a0 += h0.x*w0 + h1.x*w1 + h2.x*w2 + h3.x*w3;
        a1 += h0.y*w0 + h1.y*w1 + h2.y*w2 + h3.y*w3;
    }
    for (; p < end; p++) {
        int2 pk = g_epack[p];
        float w = __int_as_float(pk.y);
        float2 h = *(const float2*)&g_hp[(size_t)pk.x * HID + f];
        wsum += w;
        a0 += h.x * w;
        a1 += h.y * w;
    }
    float inv = 1.f / wsum;
    float v0 = a0 * inv + bg[f];
    float v1 = a1 * inv + bg[f + 1];
    *(float2*)&g_embP[(size_t)d*HID + f] = make_float2(v0, v1);
    __half h0 = __float2half(v0);
    __half l0 = __float2half(v0 - __half2float(h0));
    __half h1 = __float2half(v1);
    __half l1 = __float2half(v1 - __half2float(h1));
    size_t eb = (size_t)d * KS;
    __half2* Eh = (__half2*)&g_Ehf[eb + f];
    __half2* El = (__half2*)&g_Ehf[eb + 64 + f];
    *Eh = __halves2half2(h0, h1);
    *El = __halves2half2(l0, l1);
}

__global__ __launch_bounds__(256) void k_attr2(const float* __restrict__ b1,
                                               const float* __restrict__ W2,
                                               const float* __restrict__ b2) {
    __shared__ float xa1[IN_DIMS*EMB];
    __shared__ float W2s[EMB*HID];
    int t = threadIdx.x;
    for (int i = t; i < IN_DIMS*EMB; i += 256)
        xa1[i] = fmaxf(g_attr_part[i] + b1[i % EMB], 0.f);
    for (int i = t; i < EMB*HID; i += 256) W2s[i] = W2[i];
    __syncthreads();
    int i0 = (t >> 4) * 8;
    int h0 = (t & 15) * 4;
    float acc[8][4];
    #pragma unroll
    for (int a = 0; a < 8; a++)
        #pragma unroll
        for (int b = 0; b < 4; b++) acc[a][b] = 0.f;
    for (int k = 0; k < EMB; k++) {
        float wv[4];
        #pragma unroll
        for (int j = 0; j < 4; j++) wv[j] = W2s[k*HID + h0 + j];
        #pragma unroll
        for (int ii = 0; ii < 8; ii++) {
            float xv = xa1[(i0+ii)*EMB + k];
            #pragma unroll
            for (int j = 0; j < 4; j++) acc[ii][j] += xv * wv[j];
        }
    }
    #pragma unroll
    for (int ii = 0; ii < 8; ii++)
        #pragma unroll
        for (int j = 0; j < 4; j++)
            g_xa2[(i0+ii)*HID + h0 + j] = acc[ii][j] + b2[h0 + j];
}

__global__ __launch_bounds__(256) void k_xout(float* __restrict__ out) {
    __shared__ float xa[IN_DIMS*(HID+1)];
    __shared__ float es[32*HID];
    int t = threadIdx.x;
    for (int i = t; i < IN_DIMS*HID; i += 256) {
        int r = i / HID, c = i % HID;
        xa[r*(HID+1) + c] = g_xa2[i];
    }
    int nb = blockIdx.x * 32;
    for (int i = t; i < 32*HID; i += 256) es[i] = g_embP[(size_t)nb*HID + i];
    __syncthreads();
    int nl = t >> 3;
    int ib = (t & 7) * 16;
    const float* e = &es[nl*HID];
    int n = nb + nl;
    if (n >= N_NODES) return;
    for (int ii = 0; ii < 16; ii++) {
        int i = ib + ii;
        const float* w = &xa[i*(HID+1)];
        float acc = 0.f;
        #pragma unroll 8
        for (int k = 0; k < HID; k++) acc += e[k]*w[k];
        out[(size_t)n*IN_DIMS + i] = acc;
    }
}

// ===== s_ GEMM: 512 thr, tanh-sigmoid epilogue =====
#define ROWB 272
#define ROWB_B 144
#define BOFF 34816
#define SMEM_S 69632
#define TRS 132

__device__ __forceinline__ uint32_t smem_u32(const void* p) {
    uint32_t a;
    asm("{ .reg .u64 t; cvta.to.shared.u64 t, %1; cvt.u32.u64 %0, t; }" : "=r"(a) : "l"(p));
    return a;
}
__device__ __forceinline__ void ldsm4(uint32_t addr, uint32_t& r0, uint32_t& r1,
                                      uint32_t& r2, uint32_t& r3) {
    asm volatile("ldmatrix.sync.aligned.m8n8.x4.shared.b16 {%0,%1,%2,%3}, [%4];"
                 : "=r"(r0), "=r"(r1), "=r"(r2), "=r"(r3) : "r"(addr));
}
__device__ __forceinline__ void mma_f32(float c[4], uint32_t a0, uint32_t a1,
                                        uint32_t a2, uint32_t a3,
                                        uint32_t b0, uint32_t b1) {
    asm volatile(
        "mma.sync.aligned.m16n8k16.row.col.f32.f16.f16.f32 "
        "{%0,%1,%2,%3}, {%4,%5,%6,%7}, {%8,%9}, {%0,%1,%2,%3};"
        : "+f"(c[0]), "+f"(c[1]), "+f"(c[2]), "+f"(c[3])
        : "r"(a0), "r"(a1), "r"(a2), "r"(a3), "r"(b0), "r"(b1));
}

extern __shared__ char smem_s[];

__global__ __launch_bounds__(512, 2) void k_s_mma(float* __restrict__ sout) {
    int b = blockIdx.x;
    int ti = 0;
    {
        int rem = b, rowlen = NT;
        while (rem >= rowlen) { rem -= rowlen; ti++; rowlen--; }
        b = rem;
    }
    int tj = ti + b;

    int t = threadIdx.x;
    int warp = t >> 5, lane = t & 31;
    int wm = warp >> 1, wn = warp & 1;
    int g = lane >> 2, tq = lane & 3;
    int q = lane >> 3, r8 = lane & 7;

    const __half* gA = &g_Ehf[(size_t)ti * TILE * KS];
    const __half* gB = &g_Ehf[(size_t)tj * TILE * KS];
    #pragma unroll
    for (int i = 0; i < 4; i++) {
        int v = i * 512 + t;
        int row = v >> 4;
        int c16 = v & 15;
        *(float4*)(smem_s + row*ROWB + c16*16) = *(const float4*)(gA + row*KS + c16*8);
    }
    #pragma unroll
    for (int i = 0; i < 2; i++) {
        int v = i * 512 + t;
        int row = v >> 3;
        int c8 = v & 7;
        *(float4*)(smem_s + BOFF + row*ROWB_B + c8*16) = *(const float4*)(gB + row*KS + c8*8);
    }
    __syncthreads();

    uint32_t sA = smem_u32(smem_s);
    uint32_t sB = sA + BOFF;

    uint32_t aAddr = sA + (uint32_t)(wm*16 + r8 + (q & 1)*8)*ROWB + (uint32_t)((q >> 1)*8)*2;
    uint32_t bAddr[4];
    #pragma unroll
    for (int n2 = 0; n2 < 4; n2++)
        bAddr[n2] = sB + (uint32_t)(wn*64 + n2*16 + r8 + (q >> 1)*8)*ROWB_B + (uint32_t)((q & 1)*8)*2;

    float c[8][4];
    #pragma unroll
    for (int nt = 0; nt < 8; nt++)
        #pragma unroll
        for (int rr = 0; rr < 4; rr++) c[nt][rr] = 0.f;

    #pragma unroll
    for (int kk = 0; kk < 4; kk++) {
        uint32_t ka = (uint32_t)kk * 32;
        uint32_t ah[4], al[4];
        ldsm4(aAddr + ka,       ah[0], ah[1], ah[2], ah[3]);
        ldsm4(aAddr + 128 + ka, al[0], al[1], al[2], al[3]);
        #pragma unroll
        for (int n2 = 0; n2 < 4; n2++) {
            uint32_t b0, b1, b2, b3;
            ldsm4(bAddr[n2] + ka, b0, b1, b2, b3);
            int nt = n2 * 2;
            mma_f32(c[nt],   ah[0], ah[1], ah[2], ah[3], b0, b1);
            mma_f32(c[nt+1], ah[0], ah[1], ah[2], ah[3], b2, b3);
            mma_f32(c[nt],   al[0], al[1], al[2], al[3], b0, b1);
            mma_f32(c[nt+1], al[0], al[1], al[2], al[3], b2, b3);
        }
    }

    // sigmoid via hardware tanh (1 MUFU/elem instead of EX2+RCP)
    #pragma unroll
    for (int nt = 0; nt < 8; nt++)
        #pragma unroll
        for (int rr = 0; rr < 4; rr++)
            c[nt][rr] = fsigmoid(c[nt][rr]);

    // normal tile: direct row-major float2 stores
    #pragma unroll
    for (int rr = 0; rr < 2; rr++) {
        int gr = ti*TILE + wm*16 + g + rr*8;
        if (gr >= N_NODES) continue;
        size_t obase = (size_t)gr * N_NODES;
        #pragma unroll
        for (int nt = 0; nt < 8; nt++) {
            int gc = tj*TILE + wn*64 + nt*8 + tq*2;
            if (gc < N_NODES)
                *(float2*)&sout[obase + gc] =
                    make_float2(c[nt][rr*2], c[nt][rr*2 + 1]);
        }
    }

    // mirror tile via smem transpose stage
    if (ti != tj) {
        __syncthreads();
        float* tr = (float*)smem_s;
        #pragma unroll
        for (int rr = 0; rr < 2; rr++) {
            int lr = wm*16 + g + rr*8;
            #pragma unroll
            for (int nt = 0; nt < 8; nt++) {
                int lc = wn*64 + nt*8 + tq*2;
                tr[lc*TRS + lr]     = c[nt][rr*2];
                tr[(lc+1)*TRS + lr] = c[nt][rr*2 + 1];
            }
        }
        __syncthreads();
        int len = N_NODES - ti*TILE;
        if (len > TILE) len = TILE;
        int lr0 = lane * 4;
        #pragma unroll
        for (int rr2 = 0; rr2 < 8; rr2++) {
            int lc = warp*8 + rr2;
            int gcRow = tj*TILE + lc;
            if (gcRow < N_NODES && lr0 < len) {
                *(float4*)&sout[(size_t)gcRow*N_NODES + ti*TILE + lr0] =
                    *(float4*)&tr[lc*TRS + lr0];
            }
        }
    }
}

// ---------------- launch ----------------
extern "C" void kernel_launch(void* const* d_in, const int* in_sizes, int n_in,
                              void* d_out, int out_size) {
    const float* x       = (const float*)d_in[0];
    const int*   ei      = (const int*)d_in[1];
    const float* W_stru  = (const float*)d_in[3];
    const float* b_stru  = (const float*)d_in[4];
    const float* W_gat   = (const float*)d_in[5];
    const float* att_src = (const float*)d_in[6];
    const float* att_dst = (const float*)d_in[7];
    const float* b_gat   = (const float*)d_in[8];
    const float* W_attr1 = (const float*)d_in[9];
    const float* b_attr1 = (const float*)d_in[10];
    const float* W_attr2 = (const float*)d_in[11];
    const float* b_attr2 = (const float*)d_in[12];

    int E = in_sizes[1] / 2;
    int EN = E + N_NODES;

    float* out   = (float*)d_out;
    float* x_out = out;
    float* s_out = out + (size_t)N_NODES * IN_DIMS;

    cudaFuncSetAttribute(k_enc, cudaFuncAttributeMaxDynamicSharedMemorySize, 73728);
    cudaFuncSetAttribute(k_s_mma, cudaFuncAttributeMaxDynamicSharedMemorySize, SMEM_S);

    k_edge1 <<<(EN + 255) / 256, 256>>>(ei, E);
    k_scan  <<<1, 1024>>>();
    k_enc   <<<(N_NODES + 31) / 32, 256, 73728>>>(x, W_stru, b_stru, W_gat, att_src, att_dst);
    k_attr1 <<<N_NODES / A1_ROWS, 256>>>(x, W_attr1);
    k_edge2 <<<(EN + 255) / 256, 256>>>(ei, E);
    k_aggr  <<<(N_NODES * 32 + 255) / 256, 256>>>(b_gat);
    k_attr2 <<<1, 256>>>(b_attr1, W_attr2, b_attr2);
    k_xout  <<<(N_NODES + 31) / 32, 256>>>(x_out);
    k_s_mma <<<NT * (NT + 1) / 2, 512, SMEM_S>>>(s_out);
}

// round 16
// speedup vs baseline: 1.7518x; 1.3441x over previous
#include <cuda_runtime.h>
#include <cuda_fp16.h>
#include <math.h>
#include <stdint.h>

#define N_NODES 10000
#define IN_DIMS 128
#define EMB 64
#define HID 64
#define NEG_SLOPE 0.2f
#define TILE 128
#define NT 79
#define NPAD (NT*TILE)
#define MAXEDGE 400000
#define KS 128                // [hi(64) | lo(64)] fp16 split rows

// ---------------- scratch ----------------
__device__ float    g_hp[N_NODES*HID];
__device__ float    g_asrc[N_NODES];
__device__ float    g_adst[N_NODES];
__device__ float    g_embP[N_NODES*HID];
__device__ float    g_attr_part[IN_DIMS*EMB];
__device__ __align__(16) __half g_Ehf[NPAD*KS];
__device__ __align__(16) __half g_X2hf[IN_DIMS*KS];  // xa2 fp16, hi in cols 0..63
__device__ int g_deg[N_NODES];
__device__ int g_off[N_NODES + 1];
__device__ int g_pos[N_NODES];
__device__ int2 g_epack[MAXEDGE + N_NODES];

// fast sigmoid: 0.5*tanh(x/2)+0.5
__device__ __forceinline__ float fsigmoid(float x) {
    float th;
    asm("tanh.approx.f32 %0, %1;" : "=f"(th) : "f"(x * 0.5f));
    return fmaf(th, 0.5f, 0.5f);
}

// ===== 3-barrier block scan; self-cleans deg =====
__global__ __launch_bounds__(1024) void k_scan() {
    __shared__ int wsum[32];
    int t = threadIdx.x, lane = t & 31, wid = t >> 5;
    int base = t * 10;
    int v[10];
    int tot = 0;
    #pragma unroll
    for (int j = 0; j < 10; j++) {
        int idx = base + j;
        v[j] = (idx < N_NODES) ? g_deg[idx] : 0;
        tot += v[j];
    }
    int s = tot;
    #pragma unroll
    for (int o = 1; o < 32; o <<= 1) {
        int nv = __shfl_up_sync(0xffffffffu, s, o);
        if (lane >= o) s += nv;
    }
    if (lane == 31) wsum[wid] = s;
    __syncthreads();
    if (wid == 0) {
        int ws = wsum[lane];
        #pragma unroll
        for (int o = 1; o < 32; o <<= 1) {
            int nv = __shfl_up_sync(0xffffffffu, ws, o);
            if (lane >= o) ws += nv;
        }
        wsum[lane] = ws;
    }
    __syncthreads();
    int wex = wid ? wsum[wid - 1] : 0;
    int run = wex + s - tot;
    #pragma unroll
    for (int j = 0; j < 10; j++) {
        int idx = base + j;
        if (idx < N_NODES) {
            g_off[idx] = run;
            g_pos[idx] = run;
            g_deg[idx] = 0;
            run += v[j];
            if (idx == N_NODES - 1) g_off[N_NODES] = run;
        }
    }
}

// ===== attr1 (+ fused edge degree count): 250 blocks x 40 rows =====
#define A1_ROWS 40
__global__ __launch_bounds__(256) void k_attr1(const float* __restrict__ x,
                                               const float* __restrict__ W1,
                                               const int* __restrict__ ei, int E) {
    __shared__ float xs[A1_ROWS*IN_DIMS];
    __shared__ float ws[A1_ROWS*EMB];
    int t = threadIdx.x;
    int rbase = blockIdx.x * A1_ROWS;
    #pragma unroll
    for (int i = 0; i < 5; i++)
        ((float4*)xs)[t + i*256] =
            ((const float4*)x)[(size_t)rbase*32 + t + i*256];
    #pragma unroll
    for (int i = 0; i < 3; i++) {
        int v = t + i*256;
        if (v < A1_ROWS*EMB/4)
            ((float4*)ws)[v] = ((const float4*)W1)[(size_t)rbase*16 + v];
    }
    // fused degree counting (overlaps the smem load latency)
    {
        int EN = E + N_NODES;
        int gid = blockIdx.x * 256 + t;
        for (int i = gid; i < EN; i += 250*256) {
            int d = (i < E) ? ei[E + i] : (i - E);
            atomicAdd(&g_deg[d], 1);
        }
    }
    __syncthreads();
    int i0 = (t >> 4) * 8;
    int e0 = (t & 15) * 4;
    float acc[8][4];
    #pragma unroll
    for (int a = 0; a < 8; a++)
        #pragma unroll
        for (int b = 0; b < 4; b++) acc[a][b] = 0.f;
    #pragma unroll 4
    for (int rr = 0; rr < A1_ROWS; rr++) {
        float wv[4];
        #pragma unroll
        for (int j = 0; j < 4; j++) wv[j] = ws[rr*EMB + e0 + j];
        #pragma unroll
        for (int ii = 0; ii < 8; ii++) {
            float xv = xs[rr*IN_DIMS + i0 + ii];
            #pragma unroll
            for (int j = 0; j < 4; j++) acc[ii][j] += xv * wv[j];
        }
    }
    #pragma unroll
    for (int ii = 0; ii < 8; ii++)
        #pragma unroll
        for (int j = 0; j < 4; j++)
            atomicAdd(&g_attr_part[(i0+ii)*EMB + e0 + j], acc[ii][j]);
}

// ===== attr2: xa2 = relu(attr_part+b1)@W2 + b2 -> fp16 hi; re-zeroes attr_part =====
__global__ __launch_bounds__(256) void k_attr2(const float* __restrict__ b1,
                                               const float* __restrict__ W2,
                                               const float* __restrict__ b2) {
    __shared__ float xa1[IN_DIMS*EMB];
    __shared__ float W2s[EMB*HID];
    int t = threadIdx.x;
    for (int i = t; i < IN_DIMS*EMB; i += 256) {
        xa1[i] = fmaxf(g_attr_part[i] + b1[i % EMB], 0.f);
        g_attr_part[i] = 0.f;                 // self-clean for next replay
    }
    for (int i = t; i < EMB*HID; i += 256) W2s[i] = W2[i];
    __syncthreads();
    int i0 = (t >> 4) * 8;
    int h0 = (t & 15) * 4;
    float acc[8][4];
    #pragma unroll
    for (int a = 0; a < 8; a++)
        #pragma unroll
        for (int b = 0; b < 4; b++) acc[a][b] = 0.f;
    for (int k = 0; k < EMB; k++) {
        float wv[4];
        #pragma unroll
        for (int j = 0; j < 4; j++) wv[j] = W2s[k*HID + h0 + j];
        #pragma unroll
        for (int ii = 0; ii < 8; ii++) {
            float xv = xa1[(i0+ii)*EMB + k];
            #pragma unroll
            for (int j = 0; j < 4; j++) acc[ii][j] += xv * wv[j];
        }
    }
    #pragma unroll
    for (int ii = 0; ii < 8; ii++)
        #pragma unroll
        for (int j = 0; j < 4; j++)
            g_X2hf[(i0+ii)*KS + h0 + j] =
                __float2half(acc[ii][j] + b2[h0 + j]);
}

// ===== fused encoder, 256 thr / 32 nodes =====
extern __shared__ float s_enc[];
__global__ __launch_bounds__(256) void k_enc(const float* __restrict__ x,
                                             const float* __restrict__ W1,
                                             const float* __restrict__ b1,
                                             const float* __restrict__ W2,
                                             const float* __restrict__ att_s,
                                             const float* __restrict__ att_d) {
    float* Ws1 = s_enc;
    float* Ws2 = s_enc + 8192;
    float* xs  = s_enc + 12288;
    float* hs  = s_enc + 16384;
    __shared__ float As[HID], Ad[HID], Bs1[EMB];

    int t = threadIdx.x;
    int nbase = blockIdx.x * 32;

    #pragma unroll
    for (int i = 0; i < 8; i++)
        ((float4*)Ws1)[t + i*256] = ((const float4*)W1)[t + i*256];
    #pragma unroll
    for (int i = 0; i < 4; i++)
        ((float4*)Ws2)[t + i*256] = ((const float4*)W2)[t + i*256];
    #pragma unroll
    for (int i = 0; i < 4; i++) {
        int v = t + i*256;
        int n = nbase + (v >> 5);
        ((float4*)xs)[v] = (n < N_NODES)
            ? ((const float4*)x)[(size_t)nbase*32 + v] : make_float4(0,0,0,0);
    }
    if (t < HID) { As[t] = att_s[t]; Ad[t] = att_d[t]; }
    else if (t < 128) { Bs1[t - HID] = b1[t - HID]; }
    __syncthreads();

    int nl = t >> 4;
    int e0 = (t & 15) * 4;

    #pragma unroll
    for (int it = 0; it < 2; it++) {
        int row = nl + it*16;
        float a0=0.f, a1=0.f, a2=0.f, a3=0.f;
        const float* xr = &xs[row*IN_DIMS];
        #pragma unroll 4
        for (int k = 0; k < IN_DIMS; k++) {
            float xv = xr[k];
            float4 w = *(const float4*)&Ws1[k*EMB + e0];
            a0 += xv*w.x; a1 += xv*w.y; a2 += xv*w.z; a3 += xv*w.w;
        }
        *(float4*)&hs[row*EMB + e0] = make_float4(
            fmaxf(a0 + Bs1[e0+0], 0.f), fmaxf(a1 + Bs1[e0+1], 0.f),
            fmaxf(a2 + Bs1[e0+2], 0.f), fmaxf(a3 + Bs1[e0+3], 0.f));
    }
    __syncthreads();

    #pragma unroll
    for (int it = 0; it < 2; it++) {
        int row = nl + it*16;
        int n = nbase + row;
        float a0=0.f, a1=0.f, a2=0.f, a3=0.f;
        const float* hr = &hs[row*EMB];
        #pragma unroll 8
        for (int k = 0; k < EMB; k++) {
            float hv = hr[k];
            float4 w = *(const float4*)&Ws2[k*HID + e0];
            a0 += hv*w.x; a1 += hv*w.y; a2 += hv*w.z; a3 += hv*w.w;
        }
        if (n < N_NODES)
            *(float4*)&g_hp[(size_t)n*HID + e0] = make_float4(a0, a1, a2, a3);
        float ps = a0*As[e0] + a1*As[e0+1] + a2*As[e0+2] + a3*As[e0+3];
        float pd = a0*Ad[e0] + a1*Ad[e0+1] + a2*Ad[e0+2] + a3*Ad[e0+3];
        #pragma unroll
        for (int o = 8; o; o >>= 1) {
            ps += __shfl_down_sync(0xffffffffu, ps, o, 16);
            pd += __shfl_down_sync(0xffffffffu, pd, o, 16);
        }
        if ((t & 15) == 0 && n < N_NODES) { g_asrc[n] = ps; g_adst[n] = pd; }
    }
}

// ===== weight + scatter =====
__global__ void k_edge2(const int* __restrict__ ei, int E) {
    int i = blockIdx.x * blockDim.x + threadIdx.x;
    if (i >= E + N_NODES) return;
    int s, d;
    if (i < E) { s = ei[i]; d = ei[E + i]; } else { s = d = i - E; }
    float e = g_asrc[s] + g_adst[d];
    e = (e > 0.f) ? e : NEG_SLOPE * e;
    float w = __expf(e);
    int pos = atomicAdd(&g_pos[d], 1);
    g_epack[pos] = make_int2(s, __float_as_int(w));
}

// ===== warp per dst: float2 gathers =====
__global__ void k_aggr(const float* __restrict__ bg) {
    int d = (blockIdx.x * blockDim.x + threadIdx.x) >> 5;
    int lane = threadIdx.x & 31;
    if (d >= N_NODES) return;
    int beg = g_off[d], end = g_off[d + 1];
    float wsum = 0.f, a0 = 0.f, a1 = 0.f;
    int f = lane * 2;
    int p = beg;
    for (; p + 4 <= end; p += 4) {
        int2 e0 = g_epack[p];
        int2 e1 = g_epack[p+1];
        int2 e2 = g_epack[p+2];
        int2 e3 = g_epack[p+3];
        float2 h0 = *(const float2*)&g_hp[(size_t)e0.x * HID + f];
        float2 h1 = *(const float2*)&g_hp[(size_t)e1.x * HID + f];
        float2 h2 = *(const float2*)&g_hp[(size_t)e2.x * HID + f];
        float2 h3 = *(const float2*)&g_hp[(size_t)e3.x * HID + f];
        float w0 = __int_as_float(e0.y);
        float w1 = __int_as_float(e1.y);
        float w2 = __int_as_float(e2.y);
        float w3 = __int_as_float(e3.y);
        wsum += (w0 + w1) + (w2 + w3);
        a0 += h0.x*w0 + h1.x*w1 + h2.x*w2 + h3.x*w3;
        a1 += h0.y*w0 + h1.y*w1 + h2.y*w2 + h3.y*w3;
    }
    for (; p < end; p++) {
        int2 pk = g_epack[p];
        float w = __int_as_float(pk.y);
        float2 h = *(const float2*)&g_hp[(size_t)pk.x * HID + f];
        wsum += w;
        a0 += h.x * w;
        a1 += h.y * w;
    }
    float inv = 1.f / wsum;
    float v0 = a0 * inv + bg[f];
    float v1 = a1 * inv + bg[f + 1];
    *(float2*)&g_embP[(size_t)d*HID + f] = make_float2(v0, v1);
    __half h0 = __float2half(v0);
    __half l0 = __float2half(v0 - __half2float(h0));
    __half h1 = __float2half(v1);
    __half l1 = __float2half(v1 - __half2float(h1));
    size_t eb = (size_t)d * KS;
    *(__half2*)&g_Ehf[eb + f]      = __halves2half2(h0, h1);
    *(__half2*)&g_Ehf[eb + 64 + f] = __halves2half2(l0, l1);
}

// ===== s_ GEMM + fused x_ on diagonal blocks =====
#define ROWB 272
#define ROWB_B 144
#define BOFF 34816
#define SMEM_S 69632
#define TRS 132

__device__ __forceinline__ uint32_t smem_u32(const void* p) {
    uint32_t a;
    asm("{ .reg .u64 t; cvta.to.shared.u64 t, %1; cvt.u32.u64 %0, t; }" : "=r"(a) : "l"(p));
    return a;
}
__device__ __forceinline__ void ldsm4(uint32_t addr, uint32_t& r0, uint32_t& r1,
                                      uint32_t& r2, uint32_t& r3) {
    asm volatile("ldmatrix.sync.aligned.m8n8.x4.shared.b16 {%0,%1,%2,%3}, [%4];"
                 : "=r"(r0), "=r"(r1), "=r"(r2), "=r"(r3) : "r"(addr));
}
__device__ __forceinline__ void mma_f32(float c[4], uint32_t a0, uint32_t a1,
                                        uint32_t a2, uint32_t a3,
                                        uint32_t b0, uint32_t b1) {
    asm volatile(
        "mma.sync.aligned.m16n8k16.row.col.f32.f16.f16.f32 "
        "{%0,%1,%2,%3}, {%4,%5,%6,%7}, {%8,%9}, {%0,%1,%2,%3};"
        : "+f"(c[0]), "+f"(c[1]), "+f"(c[2]), "+f"(c[3])
        : "r"(a0), "r"(a1), "r"(a2), "r"(a3), "r"(b0), "r"(b1));
}

extern __shared__ char smem_s[];

__global__ __launch_bounds__(512, 2) void k_s_mma(float* __restrict__ sout,
                                                  float* __restrict__ xout) {
    int b = blockIdx.x;
    int ti = 0;
    {
        int rem = b, rowlen = NT;
        while (rem >= rowlen) { rem -= rowlen; ti++; rowlen--; }
        b = rem;
    }
    int tj = ti + b;

    int t = threadIdx.x;
    int warp = t >> 5, lane = t & 31;
    int wm = warp >> 1, wn = warp & 1;
    int g = lane >> 2, tq = lane & 3;
    int q = lane >> 3, r8 = lane & 7;

    const __half* gA = &g_Ehf[(size_t)ti * TILE * KS];
    const __half* gB = &g_Ehf[(size_t)tj * TILE * KS];
    #pragma unroll
    for (int i = 0; i < 4; i++) {
        int v = i * 512 + t;
        int row = v >> 4;
        int c16 = v & 15;
        *(float4*)(smem_s + row*ROWB + c16*16) = *(const float4*)(gA + row*KS + c16*8);
    }
    #pragma unroll
    for (int i = 0; i < 2; i++) {
        int v = i * 512 + t;
        int row = v >> 3;
        int c8 = v & 7;
        *(float4*)(smem_s + BOFF + row*ROWB_B + c8*16) = *(const float4*)(gB + row*KS + c8*8);
    }
    __syncthreads();

    uint32_t sA = smem_u32(smem_s);
    uint32_t sB = sA + BOFF;

    uint32_t aAddr = sA + (uint32_t)(wm*16 + r8 + (q & 1)*8)*ROWB + (uint32_t)((q >> 1)*8)*2;
    uint32_t bAddr[4];
    #pragma unroll
    for (int n2 = 0; n2 < 4; n2++)
        bAddr[n2] = sB + (uint32_t)(wn*64 + n2*16 + r8 + (q >> 1)*8)*ROWB_B + (uint32_t)((q & 1)*8)*2;

    float c[8][4];
    #pragma unroll
    for (int nt = 0; nt < 8; nt++)
        #pragma unroll
        for (int rr = 0; rr < 4; rr++) c[nt][rr] = 0.f;

    #pragma unroll
    for (int kk = 0; kk < 4; kk++) {
        uint32_t ka = (uint32_t)kk * 32;
        uint32_t ah[4], al[4];
        ldsm4(aAddr + ka,       ah[0], ah[1], ah[2], ah[3]);
        ldsm4(aAddr + 128 + ka, al[0], al[1], al[2], al[3]);
        #pragma unroll
        for (int n2 = 0; n2 < 4; n2++) {
            uint32_t b0, b1, b2, b3;
            ldsm4(bAddr[n2] + ka, b0, b1, b2, b3);
            int nt = n2 * 2;
            mma_f32(c[nt],   ah[0], ah[1], ah[2], ah[3], b0, b1);
            mma_f32(c[nt+1], ah[0], ah[1], ah[2], ah[3], b2, b3);
            mma_f32(c[nt],   al[0], al[1], al[2], al[3], b0, b1);
            mma_f32(c[nt+1], al[0], al[1], al[2], al[3], b2, b3);
        }
    }

    #pragma unroll
    for (int nt = 0; nt < 8; nt++)
        #pragma unroll
        for (int rr = 0; rr < 4; rr++)
            c[nt][rr] = fsigmoid(c[nt][rr]);

    // normal tile: direct row-major float2 stores
    #pragma unroll
    for (int rr = 0; rr < 2; rr++) {
        int gr = ti*TILE + wm*16 + g + rr*8;
        if (gr >= N_NODES) continue;
        size_t obase = (size_t)gr * N_NODES;
        #pragma unroll
        for (int nt = 0; nt < 8; nt++) {
            int gc = tj*TILE + wn*64 + nt*8 + tq*2;
            if (gc < N_NODES)
                *(float2*)&sout[obase + gc] =
                    make_float2(c[nt][rr*2], c[nt][rr*2 + 1]);
        }
    }

    if (ti != tj) {
        // mirror tile via smem transpose stage
        __syncthreads();
        float* tr = (float*)smem_s;
        #pragma unroll
        for (int rr = 0; rr < 2; rr++) {
            int lr = wm*16 + g + rr*8;
            #pragma unroll
            for (int nt = 0; nt < 8; nt++) {
                int lc = wn*64 + nt*8 + tq*2;
                tr[lc*TRS + lr]     = c[nt][rr*2];
                tr[(lc+1)*TRS + lr] = c[nt][rr*2 + 1];
            }
        }
        __syncthreads();
        int len = N_NODES - ti*TILE;
        if (len > TILE) len = TILE;
        int lr0 = lane * 4;
        #pragma unroll
        for (int rr2 = 0; rr2 < 8; rr2++) {
            int lc = warp*8 + rr2;
            int gcRow = tj*TILE + lc;
            if (gcRow < N_NODES && lr0 < len) {
                *(float4*)&sout[(size_t)gcRow*N_NODES + ti*TILE + lr0] =
                    *(float4*)&tr[lc*TRS + lr0];
            }
        }
    } else {
        // diagonal: fused x_ tile = embP_tile @ xa2^T (reuse A smem + c regs)
        __syncthreads();
        #pragma unroll
        for (int i = 0; i < 2; i++) {
            int v = i * 512 + t;
            int row = v >> 3;
            int c8 = v & 7;
            *(float4*)(smem_s + BOFF + row*ROWB_B + c8*16) =
                *(const float4*)(g_X2hf + row*KS + c8*8);
        }
        __syncthreads();
        #pragma unroll
        for (int nt = 0; nt < 8; nt++)
            #pragma unroll
            for (int rr = 0; rr < 4; rr++) c[nt][rr] = 0.f;
        #pragma unroll
        for (int kk = 0; kk < 4; kk++) {
            uint32_t ka = (uint32_t)kk * 32;
            uint32_t ah[4], al[4];
            ldsm4(aAddr + ka,       ah[0], ah[1], ah[2], ah[3]);
            ldsm4(aAddr + 128 + ka, al[0], al[1], al[2], al[3]);
            #pragma unroll
            for (int n2 = 0; n2 < 4; n2++) {
                uint32_t b0, b1, b2, b3;
                ldsm4(bAddr[n2] + ka, b0, b1, b2, b3);
                int nt = n2 * 2;
                mma_f32(c[nt],   ah[0], ah[1], ah[2], ah[3], b0, b1);
                mma_f32(c[nt+1], ah[0], ah[1], ah[2], ah[3], b2, b3);
                mma_f32(c[nt],   al[0], al[1], al[2], al[3], b0, b1);
                mma_f32(c[nt+1], al[0], al[1], al[2], al[3], b2, b3);
            }
        }
        #pragma unroll
        for (int rr = 0; rr < 2; rr++) {
            int gr = ti*TILE + wm*16 + g + rr*8;
            if (gr >= N_NODES) continue;
            size_t obase = (size_t)gr * IN_DIMS;
            #pragma unroll
            for (int nt = 0; nt < 8; nt++) {
                int gc = wn*64 + nt*8 + tq*2;
                *(float2*)&xout[obase + gc] =
                    make_float2(c[nt][rr*2], c[nt][rr*2 + 1]);
            }
        }
    }
}

// ---------------- launch ----------------
extern "C" void kernel_launch(void* const* d_in, const int* in_sizes, int n_in,
                              void* d_out, int out_size) {
    const float* x       = (const float*)d_in[0];
    const int*   ei      = (const int*)d_in[1];
    const float* W_stru  = (const float*)d_in[3];
    const float* b_stru  = (const float*)d_in[4];
    const float* W_gat   = (const float*)d_in[5];
    const float* att_src = (const float*)d_in[6];
    const float* att_dst = (const float*)d_in[7];
    const float* b_gat   = (const float*)d_in[8];
    const float* W_attr1 = (const float*)d_in[9];
    const float* b_attr1 = (const float*)d_in[10];
    const float* W_attr2 = (const float*)d_in[11];
    const float* b_attr2 = (const float*)d_in[12];

    int E = in_sizes[1] / 2;
    int EN = E + N_NODES;

    float* out   = (float*)d_out;
    float* x_out = out;
    float* s_out = out + (size_t)N_NODES * IN_DIMS;

    cudaFuncSetAttribute(k_enc, cudaFuncAttributeMaxDynamicSharedMemorySize, 73728);
    cudaFuncSetAttribute(k_s_mma, cudaFuncAttributeMaxDynamicSharedMemorySize, SMEM_S);

    k_attr1 <<<N_NODES / A1_ROWS, 256>>>(x, W_attr1, ei, E);
    k_attr2 <<<1, 256>>>(b_attr1, W_attr2, b_attr2);
    k_scan  <<<1, 1024>>>();
    k_enc   <<<(N_NODES + 31) / 32, 256, 73728>>>(x, W_stru, b_stru, W_gat, att_src, att_dst);
    k_edge2 <<<(EN + 255) / 256, 256>>>(ei, E);
    k_aggr  <<<(N_NODES * 32 + 255) / 256, 256>>>(b_gat);
    k_s_mma <<<NT * (NT + 1) / 2, 512, SMEM_S>>>(s_out, x_out);
}